// round 12
// baseline (speedup 1.0000x reference)
#include <cuda_runtime.h>
#include <cuda_fp16.h>
#include <stdint.h>
#include <math.h>

#define BATCH 4
#define CDIM 128
#define HWDIM 4096
#define NGROUP 8
#define CPG 16
#define NH 4
#define HD 32
#define OC 384   // 3*C

// Scratch (allocation-free: device globals)
__device__ float g_xn[BATCH * CDIM * HWDIM];                     // fp32 residual
__device__ __align__(16) __half g_xnh[BATCH * CDIM * HWDIM];     // fp16 [b][c][t]
__device__ __align__(16) __half g_qh[BATCH * HWDIM * CDIM];      // fp16 [b][t][128], pre-scaled Q
__device__ __align__(16) __half g_kh[BATCH * HWDIM * CDIM];      // fp16 [b][t][128] K
__device__ __align__(16) __half g_vh[BATCH * CDIM * HWDIM];      // fp16 [b][ch][t]  V
__device__ __align__(16) __half g_atth[BATCH * HWDIM * CDIM];    // fp16 [b][t][c] attn out
__device__ float g_mean[BATCH * NGROUP];
__device__ float g_rstd[BATCH * NGROUP];

__device__ __forceinline__ void mma16(float* d, const uint32_t* a, uint32_t b0, uint32_t b1) {
    asm volatile(
        "mma.sync.aligned.m16n8k16.row.col.f32.f16.f16.f32 "
        "{%0,%1,%2,%3},{%4,%5,%6,%7},{%8,%9},{%0,%1,%2,%3};\n"
        : "+f"(d[0]), "+f"(d[1]), "+f"(d[2]), "+f"(d[3])
        : "r"(a[0]), "r"(a[1]), "r"(a[2]), "r"(a[3]), "r"(b0), "r"(b1));
}

__device__ __forceinline__ void ldm4(uint32_t* r, uint32_t addr) {
    asm volatile("ldmatrix.sync.aligned.m8n8.x4.shared.b16 {%0,%1,%2,%3}, [%4];"
                 : "=r"(r[0]), "=r"(r[1]), "=r"(r[2]), "=r"(r[3]) : "r"(addr));
}

__device__ __forceinline__ void ldm4t(uint32_t* r, uint32_t addr) {
    asm volatile("ldmatrix.sync.aligned.m8n8.x4.trans.shared.b16 {%0,%1,%2,%3}, [%4];"
                 : "=r"(r[0]), "=r"(r[1]), "=r"(r[2]), "=r"(r[3]) : "r"(addr));
}

__device__ __forceinline__ uint32_t packh2(float lo, float hi) {
    __half2 h = __floats2half2_rn(lo, hi);
    return *reinterpret_cast<uint32_t*>(&h);
}

__device__ __forceinline__ uint32_t h2ex2(uint32_t x) {
    uint32_t r;
    asm("ex2.approx.f16x2 %0, %1;" : "=r"(r) : "r"(x));
    return r;
}

__device__ __forceinline__ void cpa16(uint32_t dst, const void* src) {
    asm volatile("cp.async.cg.shared.global [%0], [%1], 16;" :: "r"(dst), "l"(src));
}

__device__ __forceinline__ void sts128u(uint32_t addr, uint32_t a, uint32_t b,
                                        uint32_t c, uint32_t d) {
    asm volatile("st.shared.v4.u32 [%0], {%1,%2,%3,%4};"
                 :: "r"(addr), "r"(a), "r"(b), "r"(c), "r"(d));
}

// ---------------------------------------------------------------------------
// 1. GroupNorm statistics
// ---------------------------------------------------------------------------
__global__ void gn_stats_kernel(const float* __restrict__ x) {
    int bg = blockIdx.x;
    const float4* p = reinterpret_cast<const float4*>(x + (size_t)bg * CPG * HWDIM);
    const int n4 = CPG * HWDIM / 4;
    float s = 0.f, ss = 0.f;
    for (int i = threadIdx.x; i < n4; i += blockDim.x) {
        float4 v = p[i];
        s  += v.x + v.y + v.z + v.w;
        ss += v.x * v.x + v.y * v.y + v.z * v.z + v.w * v.w;
    }
    __shared__ float sh_s[256], sh_ss[256];
    sh_s[threadIdx.x] = s;
    sh_ss[threadIdx.x] = ss;
    __syncthreads();
    for (int off = 128; off > 0; off >>= 1) {
        if (threadIdx.x < off) {
            sh_s[threadIdx.x]  += sh_s[threadIdx.x + off];
            sh_ss[threadIdx.x] += sh_ss[threadIdx.x + off];
        }
        __syncthreads();
    }
    if (threadIdx.x == 0) {
        const float inv = 1.0f / (float)(CPG * HWDIM);
        float mean = sh_s[0] * inv;
        float var  = sh_ss[0] * inv - mean * mean;
        g_mean[bg] = mean;
        g_rstd[bg] = rsqrtf(var + 1e-5f);
    }
}

// ---------------------------------------------------------------------------
// 2. Apply GroupNorm: fp32 out (residual) + fp16 out (GEMM input)
// ---------------------------------------------------------------------------
__global__ void gn_apply_kernel(const float* __restrict__ x,
                                const float* __restrict__ w,
                                const float* __restrict__ bias) {
    int i4 = blockIdx.x * blockDim.x + threadIdx.x;
    const int total4 = BATCH * CDIM * HWDIM / 4;
    if (i4 >= total4) return;
    int e  = i4 * 4;
    int c  = (e / HWDIM) % CDIM;
    int bg = e / (CPG * HWDIM);
    float mean = g_mean[bg], rstd = g_rstd[bg];
    float sw = w[c] * rstd;
    float sb = bias[c] - mean * sw;
    float4 v = reinterpret_cast<const float4*>(x)[i4];
    float4 o;
    o.x = v.x * sw + sb;
    o.y = v.y * sw + sb;
    o.z = v.z * sw + sb;
    o.w = v.w * sw + sb;
    reinterpret_cast<float4*>(g_xn)[i4] = o;
    reinterpret_cast<__half2*>(g_xnh)[i4 * 2]     = __floats2half2_rn(o.x, o.y);
    reinterpret_cast<__half2*>(g_xnh)[i4 * 2 + 1] = __floats2half2_rn(o.z, o.w);
}

// ---------------------------------------------------------------------------
// 3. QKV GEMM, fp16 tensor cores. Out = W @ xn + bias.
//    Q -> g_qh[t][o] pre-scaled; K -> g_kh[t][o-128]; V -> g_vh[o-256][t].
// ---------------------------------------------------------------------------
#define QKV_SMEM (16384 + 32768)

__global__ void __launch_bounds__(256) qkv_h_kernel(const float* __restrict__ W,
                                                    const float* __restrict__ bias) {
    extern __shared__ char qs[];
    uint32_t ws_u, xs_u;
    asm("{ .reg .u64 t; cvta.to.shared.u64 t, %1; cvt.u32.u64 %0, t; }"
        : "=r"(ws_u) : "l"(qs));
    xs_u = ws_u + 16384;

    const int b = blockIdx.z;
    const int ob0 = blockIdx.y * 64;
    const int t0 = blockIdx.x * 128;
    const int tid = threadIdx.x, warp = tid >> 5, lane = tid & 31;
    const int lr = lane >> 2, lc = lane & 3, r8 = lane & 7, j8 = lane >> 3;

    // ---- W tile: [64 o][128 c] fp32 -> fp16, swizzled ----
    {
        int row = tid >> 2;
#pragma unroll
        for (int i = 0; i < 4; i++) {
            int g = (tid & 3) * 4 + i;
            const float* wp = W + (size_t)(ob0 + row) * CDIM + g * 8;
            float4 wa = *(const float4*)wp;
            float4 wb = *(const float4*)(wp + 4);
            sts128u(ws_u + row * 256 + ((g ^ (row & 7)) << 4),
                    packh2(wa.x, wa.y), packh2(wa.z, wa.w),
                    packh2(wb.x, wb.y), packh2(wb.z, wb.w));
        }
    }
    // ---- X tile: [128 c][128 t] fp16 via cp.async ----
    {
        int tg = tid & 15, c0 = (tid >> 4) * 8;
        const __half* xp = g_xnh + (size_t)b * CDIM * HWDIM;
#pragma unroll
        for (int j = 0; j < 8; j++) {
            int c = c0 + j;
            cpa16(xs_u + c * 256 + ((tg ^ (c & 7)) << 4),
                  xp + (size_t)c * HWDIM + t0 + tg * 8);
        }
        asm volatile("cp.async.commit_group;" ::: "memory");
    }
    asm volatile("cp.async.wait_group 0;" ::: "memory");
    __syncthreads();

    const int wm = warp & 1, wn = warp >> 1;
    float acc[4][2][4];
#pragma unroll
    for (int mi = 0; mi < 4; mi++)
#pragma unroll
        for (int n8 = 0; n8 < 2; n8++)
#pragma unroll
            for (int c = 0; c < 4; c++) acc[mi][n8][c] = 0.f;

#pragma unroll
    for (int ks = 0; ks < 4; ks++) {
        uint32_t bf[2][4];
#pragma unroll
        for (int n8 = 0; n8 < 2; n8++) {
            int row = wn * 16 + n8 * 8 + r8;
            ldm4(bf[n8], ws_u + row * 256 + (((ks * 4 + j8) ^ (row & 7)) << 4));
        }
        uint32_t af[4][2][4];
#pragma unroll
        for (int mi = 0; mi < 4; mi++)
#pragma unroll
            for (int kh = 0; kh < 2; kh++) {
                int c_row = ks * 32 + kh * 16 + (lane & 7) + ((lane >> 4) & 1) * 8;
                int tg = wm * 8 + mi * 2 + ((lane >> 3) & 1);
                ldm4t(af[mi][kh], xs_u + c_row * 256 + ((tg ^ (c_row & 7)) << 4));
            }
#pragma unroll
        for (int mi = 0; mi < 4; mi++)
#pragma unroll
            for (int n8 = 0; n8 < 2; n8++) {
                mma16(acc[mi][n8], af[mi][0], bf[n8][0], bf[n8][1]);
                mma16(acc[mi][n8], af[mi][1], bf[n8][2], bf[n8][3]);
            }
    }

    // ---- epilogue ----
    const float QSC = 0.088388347648318447f * 1.4426950408889634f;  // C^-0.5 * log2(e)
#pragma unroll
    for (int mi = 0; mi < 4; mi++) {
        int t = t0 + wm * 64 + mi * 16 + lr;
#pragma unroll
        for (int n8 = 0; n8 < 2; n8++) {
            int o = ob0 + wn * 16 + n8 * 8 + 2 * lc;
            float b0 = bias[o], b1 = bias[o + 1];
            float v0 = acc[mi][n8][0] + b0, v1 = acc[mi][n8][1] + b1;
            float v2 = acc[mi][n8][2] + b0, v3 = acc[mi][n8][3] + b1;
            if (ob0 < 128) {          // Q: [t][o], pre-scaled
                *(__half2*)(g_qh + ((size_t)b * HWDIM + t) * CDIM + o) =
                    __floats2half2_rn(v0 * QSC, v1 * QSC);
                *(__half2*)(g_qh + ((size_t)b * HWDIM + t + 8) * CDIM + o) =
                    __floats2half2_rn(v2 * QSC, v3 * QSC);
            } else if (ob0 < 256) {   // K: [t][o-128]
                *(__half2*)(g_kh + ((size_t)b * HWDIM + t) * CDIM + (o - 128)) =
                    __floats2half2_rn(v0, v1);
                *(__half2*)(g_kh + ((size_t)b * HWDIM + t + 8) * CDIM + (o - 128)) =
                    __floats2half2_rn(v2, v3);
            } else {                  // V: [ch][t]
                __half* vv = g_vh + (size_t)b * CDIM * HWDIM;
                vv[(size_t)(o - 256) * HWDIM + t]     = __float2half(v0);
                vv[(size_t)(o - 255) * HWDIM + t]     = __float2half(v1);
                vv[(size_t)(o - 256) * HWDIM + t + 8] = __float2half(v2);
                vv[(size_t)(o - 255) * HWDIM + t + 8] = __float2half(v3);
            }
        }
    }
}

// ---------------------------------------------------------------------------
// 4. Flash attention: fp16 mma, register-resident P (FA2 layout trick),
//    cp.async direct into swizzled fragment-native K/V buffers (no scatter).
//    256 threads, 8 warps x 32 q = 256 q/CTA, 64-key tiles, double buffer.
//    smem: kf[2][64 rows][64B] @0, vf[2][32 rows][128B] @8192  -> 16KB.
// ---------------------------------------------------------------------------
#define NT (HWDIM / 64)

__global__ void __launch_bounds__(256, 2) attn_mma_kernel() {
    __shared__ __align__(16) char smem[16384];
    uint32_t smem_u;
    asm("{ .reg .u64 t; cvta.to.shared.u64 t, %1; cvt.u32.u64 %0, t; }"
        : "=r"(smem_u) : "l"(smem));

    const int b = blockIdx.z, h = blockIdx.y;
    const int q0 = blockIdx.x * 256;
    const int tid = threadIdx.x;
    const int warp = tid >> 5, lane = tid & 31;
    const int lr = lane >> 2, lc = lane & 3;
    const int r8 = lane & 7, j8 = lane >> 3;
    const int qbase = warp * 32;

    const __half* Qh = g_qh + (size_t)b * HWDIM * CDIM;
    const __half* Kh = g_kh + (size_t)b * HWDIM * CDIM;
    const __half* Vh = g_vh + ((size_t)b * CDIM + h * HD) * HWDIM;

    // tile-load indices: 1 K chunk + 1 V chunk per thread
    const int lk_key = tid >> 2, lk_g = tid & 3;   // K: row=key(64), 4x16B chunks
    const int lv_ch  = tid >> 3, lv_g = tid & 7;   // V: row=ch(32), 8x16B chunks

    // ---- stage tile 0 into buf 0 ----
    cpa16(smem_u + lk_key * 64 + ((lk_g ^ ((lk_key >> 1) & 3)) << 4),
          Kh + (size_t)lk_key * CDIM + h * HD + lk_g * 8);
    cpa16(smem_u + 8192 + lv_ch * 128 + ((lv_g ^ (lv_ch & 7)) << 4),
          Vh + (size_t)lv_ch * HWDIM + lv_g * 8);
    asm volatile("cp.async.commit_group;" ::: "memory");

    // ---- Q fragments (fp16 pre-scaled) ----
    uint32_t qa[2][2][4];
#pragma unroll
    for (int mf = 0; mf < 2; mf++) {
        int qrow = q0 + qbase + mf * 16 + lr;
#pragma unroll
        for (int ks = 0; ks < 2; ks++) {
            int cc = h * HD + 2 * lc + 16 * ks;
            qa[mf][ks][0] = *(const uint32_t*)(Qh + (size_t)qrow * CDIM + cc);
            qa[mf][ks][1] = *(const uint32_t*)(Qh + (size_t)(qrow + 8) * CDIM + cc);
            qa[mf][ks][2] = *(const uint32_t*)(Qh + (size_t)qrow * CDIM + cc + 8);
            qa[mf][ks][3] = *(const uint32_t*)(Qh + (size_t)(qrow + 8) * CDIM + cc + 8);
        }
    }

    float l_i[2][2] = {{0.f, 0.f}, {0.f, 0.f}};
    float oacc[2][4][4];
#pragma unroll
    for (int mf = 0; mf < 2; mf++)
#pragma unroll
        for (int nf = 0; nf < 4; nf++)
#pragma unroll
            for (int c = 0; c < 4; c++) oacc[mf][nf][c] = 0.f;

    for (int t = 0; t < NT; t++) {
        // ---- stage tile t+1 into the other buffer ----
        if (t < NT - 1) {
            const int j0n = (t + 1) * 64;
            const int nb = (t + 1) & 1;
            cpa16(smem_u + nb * 4096 + lk_key * 64 + ((lk_g ^ ((lk_key >> 1) & 3)) << 4),
                  Kh + (size_t)(j0n + lk_key) * CDIM + h * HD + lk_g * 8);
            cpa16(smem_u + 8192 + nb * 4096 + lv_ch * 128 + ((lv_g ^ (lv_ch & 7)) << 4),
                  Vh + (size_t)lv_ch * HWDIM + j0n + lv_g * 8);
            asm volatile("cp.async.commit_group;" ::: "memory");
            asm volatile("cp.async.wait_group 1;" ::: "memory");
        } else {
            asm volatile("cp.async.wait_group 0;" ::: "memory");
        }
        __syncthreads();  // tile t visible to all threads

        const uint32_t kfb = smem_u + (t & 1) * 4096;
        const uint32_t vfb = smem_u + 8192 + (t & 1) * 4096;

        // ---- S = Q @ K^T ----
        float sacc[2][8][4];
#pragma unroll
        for (int mf = 0; mf < 2; mf++)
#pragma unroll
            for (int nf = 0; nf < 8; nf++)
#pragma unroll
                for (int c = 0; c < 4; c++) sacc[mf][nf][c] = 0.f;

#pragma unroll
        for (int nf = 0; nf < 8; nf++) {
            uint32_t kb[4];
            int row = nf * 8 + r8;
            ldm4(kb, kfb + row * 64 + ((j8 ^ ((row >> 1) & 3)) << 4));
#pragma unroll
            for (int mf = 0; mf < 2; mf++) {
                mma16(sacc[mf][nf], qa[mf][0], kb[0], kb[1]);
                mma16(sacc[mf][nf], qa[mf][1], kb[2], kb[3]);
            }
        }

        // ---- softmax: f16x2 exp2 in registers, P stays in registers ----
        uint32_t ph[2][2][8];  // [mf][row-half][nf]
#pragma unroll
        for (int mf = 0; mf < 2; mf++) {
#pragma unroll
            for (int nf = 0; nf < 8; nf++) {
                ph[mf][0][nf] = h2ex2(packh2(sacc[mf][nf][0], sacc[mf][nf][1]));
                ph[mf][1][nf] = h2ex2(packh2(sacc[mf][nf][2], sacc[mf][nf][3]));
            }
#pragma unroll
            for (int ri = 0; ri < 2; ri++) {
                const uint32_t* p = ph[mf][ri];
                __half2 s0 = __hadd2(*(__half2*)&p[0], *(__half2*)&p[1]);
                __half2 s1 = __hadd2(*(__half2*)&p[2], *(__half2*)&p[3]);
                __half2 s2 = __hadd2(*(__half2*)&p[4], *(__half2*)&p[5]);
                __half2 s3 = __hadd2(*(__half2*)&p[6], *(__half2*)&p[7]);
                __half2 s = __hadd2(__hadd2(s0, s1), __hadd2(s2, s3));
                float2 f = __half22float2(s);
                float sum = f.x + f.y;
                sum += __shfl_xor_sync(0xffffffffu, sum, 1);
                sum += __shfl_xor_sync(0xffffffffu, sum, 2);
                l_i[mf][ri] += sum;
            }
        }

        // ---- V b-frags ----
        uint32_t vb[4][2][4];
#pragma unroll
        for (int nf = 0; nf < 4; nf++)
#pragma unroll
            for (int l = 0; l < 2; l++) {
                int row = nf * 8 + r8;
                int g = l * 4 + j8;
                ldm4(vb[nf][l], vfb + row * 128 + ((g ^ r8) << 4));
            }

        // ---- O += P @ V (A-fragments direct from registers) ----
#pragma unroll
        for (int mf = 0; mf < 2; mf++) {
#pragma unroll
            for (int kq = 0; kq < 4; kq++) {
                uint32_t pa[4] = {ph[mf][0][2 * kq], ph[mf][1][2 * kq],
                                  ph[mf][0][2 * kq + 1], ph[mf][1][2 * kq + 1]};
#pragma unroll
                for (int nf = 0; nf < 4; nf++) {
                    uint32_t* vv = vb[nf][kq >> 1];
                    mma16(oacc[mf][nf], pa, vv[2 * (kq & 1)], vv[2 * (kq & 1) + 1]);
                }
            }
        }
        __syncthreads();  // all reads of buf t&1 done before it is re-staged
    }

    // ---- epilogue: fp16 [t][c] output ----
#pragma unroll
    for (int mf = 0; mf < 2; mf++)
#pragma unroll
        for (int ri = 0; ri < 2; ri++) {
            float inv = 1.f / l_i[mf][ri];
            int q = q0 + qbase + mf * 16 + lr + 8 * ri;
#pragma unroll
            for (int nf = 0; nf < 4; nf++) {
                int ch = h * HD + nf * 8 + 2 * lc;
                *(uint32_t*)(g_atth + ((size_t)b * HWDIM + q) * CDIM + ch) =
                    packh2(oacc[mf][nf][2 * ri] * inv, oacc[mf][nf][2 * ri + 1] * inv);
            }
        }
}

// ---------------------------------------------------------------------------
// 5. Projection GEMM, fp16 tensor cores + fp32 bias/residual epilogue.
//    A = g_atth [t][c] (non-trans ldmatrix), B = proj_w, Out[o][t] fp32.
// ---------------------------------------------------------------------------
#define PROJ_SMEM (16384 + 32768)

__global__ void __launch_bounds__(256) proj_h_kernel(const float* __restrict__ W,
                                                     const float* __restrict__ bias,
                                                     float* __restrict__ Out) {
    extern __shared__ char qs[];
    uint32_t ws_u, as_u;
    asm("{ .reg .u64 t; cvta.to.shared.u64 t, %1; cvt.u32.u64 %0, t; }"
        : "=r"(ws_u) : "l"(qs));
    as_u = ws_u + 16384;

    const int b = blockIdx.z;
    const int ob0 = blockIdx.y * 64;
    const int t0 = blockIdx.x * 128;
    const int tid = threadIdx.x, warp = tid >> 5, lane = tid & 31;
    const int lr = lane >> 2, lc = lane & 3, r8 = lane & 7, j8 = lane >> 3;

    // ---- W tile ----
    {
        int row = tid >> 2;
#pragma unroll
        for (int i = 0; i < 4; i++) {
            int g = (tid & 3) * 4 + i;
            const float* wp = W + (size_t)(ob0 + row) * CDIM + g * 8;
            float4 wa = *(const float4*)wp;
            float4 wb = *(const float4*)(wp + 4);
            sts128u(ws_u + row * 256 + ((g ^ (row & 7)) << 4),
                    packh2(wa.x, wa.y), packh2(wa.z, wa.w),
                    packh2(wb.x, wb.y), packh2(wb.z, wb.w));
        }
    }
    // ---- A tile: [128 t][128 c] fp16 via cp.async ----
    {
        int tg = tid & 15, row0 = tid >> 4;
        const __half* ap = g_atth + (size_t)b * HWDIM * CDIM;
#pragma unroll
        for (int j = 0; j < 8; j++) {
            int row = row0 + 16 * j;
            cpa16(as_u + row * 256 + ((tg ^ (row & 7)) << 4),
                  ap + (size_t)(t0 + row) * CDIM + tg * 8);
        }
        asm volatile("cp.async.commit_group;" ::: "memory");
    }
    asm volatile("cp.async.wait_group 0;" ::: "memory");
    __syncthreads();

    const int wm = warp & 1, wn = warp >> 1;
    float acc[4][2][4];
#pragma unroll
    for (int mi = 0; mi < 4; mi++)
#pragma unroll
        for (int n8 = 0; n8 < 2; n8++)
#pragma unroll
            for (int c = 0; c < 4; c++) acc[mi][n8][c] = 0.f;

#pragma unroll
    for (int ks = 0; ks < 4; ks++) {
        uint32_t bf[2][4];
#pragma unroll
        for (int n8 = 0; n8 < 2; n8++) {
            int row = wn * 16 + n8 * 8 + r8;
            ldm4(bf[n8], ws_u + row * 256 + (((ks * 4 + j8) ^ (row & 7)) << 4));
        }
        uint32_t af[4][2][4];
#pragma unroll
        for (int mi = 0; mi < 4; mi++)
#pragma unroll
            for (int kh = 0; kh < 2; kh++) {
                int row = wm * 64 + mi * 16 + ((j8 & 1) << 3) + r8;
                int g = ks * 4 + kh * 2 + (j8 >> 1);
                ldm4(af[mi][kh], as_u + row * 256 + ((g ^ (row & 7)) << 4));
            }
#pragma unroll
        for (int mi = 0; mi < 4; mi++)
#pragma unroll
            for (int n8 = 0; n8 < 2; n8++) {
                mma16(acc[mi][n8], af[mi][0], bf[n8][0], bf[n8][1]);
                mma16(acc[mi][n8], af[mi][1], bf[n8][2], bf[n8][3]);
            }
    }

    // ---- epilogue: fp32 + bias + residual ----
#pragma unroll
    for (int mi = 0; mi < 4; mi++) {
        int t = t0 + wm * 64 + mi * 16 + lr;
#pragma unroll
        for (int n8 = 0; n8 < 2; n8++) {
            int o = ob0 + wn * 16 + n8 * 8 + 2 * lc;
            float b0 = bias[o], b1 = bias[o + 1];
            size_t i00 = ((size_t)b * CDIM + o) * HWDIM + t;
            size_t i10 = i00 + HWDIM;
            Out[i00]     = acc[mi][n8][0] + b0 + g_xn[i00];
            Out[i10]     = acc[mi][n8][1] + b1 + g_xn[i10];
            Out[i00 + 8] = acc[mi][n8][2] + b0 + g_xn[i00 + 8];
            Out[i10 + 8] = acc[mi][n8][3] + b1 + g_xn[i10 + 8];
        }
    }
}

// ---------------------------------------------------------------------------
// Launch
// ---------------------------------------------------------------------------
extern "C" void kernel_launch(void* const* d_in, const int* in_sizes, int n_in,
                              void* d_out, int out_size) {
    const float* x      = (const float*)d_in[0];
    const float* gn_w   = (const float*)d_in[1];
    const float* gn_b   = (const float*)d_in[2];
    const float* qkv_w  = (const float*)d_in[3];
    const float* qkv_b  = (const float*)d_in[4];
    const float* proj_w = (const float*)d_in[5];
    const float* proj_b = (const float*)d_in[6];
    float* out = (float*)d_out;

    static bool attr_set = false;
    if (!attr_set) {
        cudaFuncSetAttribute(qkv_h_kernel,
                             cudaFuncAttributeMaxDynamicSharedMemorySize, QKV_SMEM);
        cudaFuncSetAttribute(proj_h_kernel,
                             cudaFuncAttributeMaxDynamicSharedMemorySize, PROJ_SMEM);
        attr_set = true;
    }

    gn_stats_kernel<<<BATCH * NGROUP, 256>>>(x);
    gn_apply_kernel<<<(BATCH * CDIM * HWDIM / 4 + 255) / 256, 256>>>(x, gn_w, gn_b);
    qkv_h_kernel<<<dim3(HWDIM / 128, OC / 64, BATCH), 256, QKV_SMEM>>>(qkv_w, qkv_b);
    attn_mma_kernel<<<dim3(HWDIM / 256, NH, BATCH), 256>>>();
    proj_h_kernel<<<dim3(HWDIM / 128, CDIM / 64, BATCH), 256, PROJ_SMEM>>>(
        proj_w, proj_b, out);
}

// round 13
// speedup vs baseline: 1.5085x; 1.5085x over previous
#include <cuda_runtime.h>
#include <cuda_fp16.h>
#include <stdint.h>
#include <math.h>

#define BATCH 4
#define CDIM 128
#define HWDIM 4096
#define NGROUP 8
#define CPG 16
#define NH 4
#define HD 32
#define OC 384   // 3*C

// Scratch (allocation-free: device globals)
__device__ float g_xn[BATCH * CDIM * HWDIM];                     // fp32 residual
__device__ __align__(16) __half g_xnh[BATCH * CDIM * HWDIM];     // fp16 [b][c][t]
__device__ __align__(16) __half g_qh[BATCH * HWDIM * CDIM];      // fp16 [b][t][128], pre-scaled Q
__device__ __align__(16) __half g_kh[BATCH * HWDIM * CDIM];      // fp16 [b][t][128] K
__device__ __align__(16) __half g_vh[BATCH * CDIM * HWDIM];      // fp16 [b][ch][t]  V
__device__ __align__(16) __half g_atth[BATCH * HWDIM * CDIM];    // fp16 [b][t][c] attn out
__device__ float g_mean[BATCH * NGROUP];
__device__ float g_rstd[BATCH * NGROUP];

__device__ __forceinline__ void mma16(float* d, const uint32_t* a, uint32_t b0, uint32_t b1) {
    asm volatile(
        "mma.sync.aligned.m16n8k16.row.col.f32.f16.f16.f32 "
        "{%0,%1,%2,%3},{%4,%5,%6,%7},{%8,%9},{%0,%1,%2,%3};\n"
        : "+f"(d[0]), "+f"(d[1]), "+f"(d[2]), "+f"(d[3])
        : "r"(a[0]), "r"(a[1]), "r"(a[2]), "r"(a[3]), "r"(b0), "r"(b1));
}

__device__ __forceinline__ void ldm4(uint32_t* r, uint32_t addr) {
    asm volatile("ldmatrix.sync.aligned.m8n8.x4.shared.b16 {%0,%1,%2,%3}, [%4];"
                 : "=r"(r[0]), "=r"(r[1]), "=r"(r[2]), "=r"(r[3]) : "r"(addr));
}

__device__ __forceinline__ void ldm4t(uint32_t* r, uint32_t addr) {
    asm volatile("ldmatrix.sync.aligned.m8n8.x4.trans.shared.b16 {%0,%1,%2,%3}, [%4];"
                 : "=r"(r[0]), "=r"(r[1]), "=r"(r[2]), "=r"(r[3]) : "r"(addr));
}

__device__ __forceinline__ uint32_t packh2(float lo, float hi) {
    __half2 h = __floats2half2_rn(lo, hi);
    return *reinterpret_cast<uint32_t*>(&h);
}

__device__ __forceinline__ uint32_t h2ex2(uint32_t x) {
    uint32_t r;
    asm("ex2.approx.f16x2 %0, %1;" : "=r"(r) : "r"(x));
    return r;
}

__device__ __forceinline__ void cpa16(uint32_t dst, const void* src) {
    asm volatile("cp.async.cg.shared.global [%0], [%1], 16;" :: "r"(dst), "l"(src));
}

__device__ __forceinline__ void sts128u(uint32_t addr, uint32_t a, uint32_t b,
                                        uint32_t c, uint32_t d) {
    asm volatile("st.shared.v4.u32 [%0], {%1,%2,%3,%4};"
                 :: "r"(addr), "r"(a), "r"(b), "r"(c), "r"(d));
}

// ---------------------------------------------------------------------------
// 1. GroupNorm statistics
// ---------------------------------------------------------------------------
__global__ void gn_stats_kernel(const float* __restrict__ x) {
    int bg = blockIdx.x;
    const float4* p = reinterpret_cast<const float4*>(x + (size_t)bg * CPG * HWDIM);
    const int n4 = CPG * HWDIM / 4;
    float s = 0.f, ss = 0.f;
    for (int i = threadIdx.x; i < n4; i += blockDim.x) {
        float4 v = p[i];
        s  += v.x + v.y + v.z + v.w;
        ss += v.x * v.x + v.y * v.y + v.z * v.z + v.w * v.w;
    }
    __shared__ float sh_s[256], sh_ss[256];
    sh_s[threadIdx.x] = s;
    sh_ss[threadIdx.x] = ss;
    __syncthreads();
    for (int off = 128; off > 0; off >>= 1) {
        if (threadIdx.x < off) {
            sh_s[threadIdx.x]  += sh_s[threadIdx.x + off];
            sh_ss[threadIdx.x] += sh_ss[threadIdx.x + off];
        }
        __syncthreads();
    }
    if (threadIdx.x == 0) {
        const float inv = 1.0f / (float)(CPG * HWDIM);
        float mean = sh_s[0] * inv;
        float var  = sh_ss[0] * inv - mean * mean;
        g_mean[bg] = mean;
        g_rstd[bg] = rsqrtf(var + 1e-5f);
    }
}

// ---------------------------------------------------------------------------
// 2. Apply GroupNorm: fp32 out (residual) + fp16 out (GEMM input)
// ---------------------------------------------------------------------------
__global__ void gn_apply_kernel(const float* __restrict__ x,
                                const float* __restrict__ w,
                                const float* __restrict__ bias) {
    int i4 = blockIdx.x * blockDim.x + threadIdx.x;
    const int total4 = BATCH * CDIM * HWDIM / 4;
    if (i4 >= total4) return;
    int e  = i4 * 4;
    int c  = (e / HWDIM) % CDIM;
    int bg = e / (CPG * HWDIM);
    float mean = g_mean[bg], rstd = g_rstd[bg];
    float sw = w[c] * rstd;
    float sb = bias[c] - mean * sw;
    float4 v = reinterpret_cast<const float4*>(x)[i4];
    float4 o;
    o.x = v.x * sw + sb;
    o.y = v.y * sw + sb;
    o.z = v.z * sw + sb;
    o.w = v.w * sw + sb;
    reinterpret_cast<float4*>(g_xn)[i4] = o;
    reinterpret_cast<__half2*>(g_xnh)[i4 * 2]     = __floats2half2_rn(o.x, o.y);
    reinterpret_cast<__half2*>(g_xnh)[i4 * 2 + 1] = __floats2half2_rn(o.z, o.w);
}

// ---------------------------------------------------------------------------
// 3. QKV GEMM, fp16 tensor cores. Out = W @ xn + bias.
//    Q -> g_qh[t][o] pre-scaled; K -> g_kh[t][o-128]; V -> g_vh[o-256][t].
// ---------------------------------------------------------------------------
#define QKV_SMEM (16384 + 32768)

__global__ void __launch_bounds__(256) qkv_h_kernel(const float* __restrict__ W,
                                                    const float* __restrict__ bias) {
    extern __shared__ char qs[];
    uint32_t ws_u, xs_u;
    asm("{ .reg .u64 t; cvta.to.shared.u64 t, %1; cvt.u32.u64 %0, t; }"
        : "=r"(ws_u) : "l"(qs));
    xs_u = ws_u + 16384;

    const int b = blockIdx.z;
    const int ob0 = blockIdx.y * 64;
    const int t0 = blockIdx.x * 128;
    const int tid = threadIdx.x, warp = tid >> 5, lane = tid & 31;
    const int lr = lane >> 2, lc = lane & 3, r8 = lane & 7, j8 = lane >> 3;

    // ---- W tile: [64 o][128 c] fp32 -> fp16, swizzled ----
    {
        int row = tid >> 2;
#pragma unroll
        for (int i = 0; i < 4; i++) {
            int g = (tid & 3) * 4 + i;
            const float* wp = W + (size_t)(ob0 + row) * CDIM + g * 8;
            float4 wa = *(const float4*)wp;
            float4 wb = *(const float4*)(wp + 4);
            sts128u(ws_u + row * 256 + ((g ^ (row & 7)) << 4),
                    packh2(wa.x, wa.y), packh2(wa.z, wa.w),
                    packh2(wb.x, wb.y), packh2(wb.z, wb.w));
        }
    }
    // ---- X tile: [128 c][128 t] fp16 via cp.async ----
    {
        int tg = tid & 15, c0 = (tid >> 4) * 8;
        const __half* xp = g_xnh + (size_t)b * CDIM * HWDIM;
#pragma unroll
        for (int j = 0; j < 8; j++) {
            int c = c0 + j;
            cpa16(xs_u + c * 256 + ((tg ^ (c & 7)) << 4),
                  xp + (size_t)c * HWDIM + t0 + tg * 8);
        }
        asm volatile("cp.async.commit_group;" ::: "memory");
    }
    asm volatile("cp.async.wait_group 0;" ::: "memory");
    __syncthreads();

    const int wm = warp & 1, wn = warp >> 1;
    float acc[4][2][4];
#pragma unroll
    for (int mi = 0; mi < 4; mi++)
#pragma unroll
        for (int n8 = 0; n8 < 2; n8++)
#pragma unroll
            for (int c = 0; c < 4; c++) acc[mi][n8][c] = 0.f;

#pragma unroll
    for (int ks = 0; ks < 4; ks++) {
        uint32_t bf[2][4];
#pragma unroll
        for (int n8 = 0; n8 < 2; n8++) {
            int row = wn * 16 + n8 * 8 + r8;
            ldm4(bf[n8], ws_u + row * 256 + (((ks * 4 + j8) ^ (row & 7)) << 4));
        }
        uint32_t af[4][2][4];
#pragma unroll
        for (int mi = 0; mi < 4; mi++)
#pragma unroll
            for (int kh = 0; kh < 2; kh++) {
                int c_row = ks * 32 + kh * 16 + (lane & 7) + ((lane >> 4) & 1) * 8;
                int tg = wm * 8 + mi * 2 + ((lane >> 3) & 1);
                ldm4t(af[mi][kh], xs_u + c_row * 256 + ((tg ^ (c_row & 7)) << 4));
            }
#pragma unroll
        for (int mi = 0; mi < 4; mi++)
#pragma unroll
            for (int n8 = 0; n8 < 2; n8++) {
                mma16(acc[mi][n8], af[mi][0], bf[n8][0], bf[n8][1]);
                mma16(acc[mi][n8], af[mi][1], bf[n8][2], bf[n8][3]);
            }
    }

    // ---- epilogue ----
    const float QSC = 0.088388347648318447f * 1.4426950408889634f;  // C^-0.5 * log2(e)
#pragma unroll
    for (int mi = 0; mi < 4; mi++) {
        int t = t0 + wm * 64 + mi * 16 + lr;
#pragma unroll
        for (int n8 = 0; n8 < 2; n8++) {
            int o = ob0 + wn * 16 + n8 * 8 + 2 * lc;
            float b0 = bias[o], b1 = bias[o + 1];
            float v0 = acc[mi][n8][0] + b0, v1 = acc[mi][n8][1] + b1;
            float v2 = acc[mi][n8][2] + b0, v3 = acc[mi][n8][3] + b1;
            if (ob0 < 128) {          // Q: [t][o], pre-scaled
                *(__half2*)(g_qh + ((size_t)b * HWDIM + t) * CDIM + o) =
                    __floats2half2_rn(v0 * QSC, v1 * QSC);
                *(__half2*)(g_qh + ((size_t)b * HWDIM + t + 8) * CDIM + o) =
                    __floats2half2_rn(v2 * QSC, v3 * QSC);
            } else if (ob0 < 256) {   // K: [t][o-128]
                *(__half2*)(g_kh + ((size_t)b * HWDIM + t) * CDIM + (o - 128)) =
                    __floats2half2_rn(v0, v1);
                *(__half2*)(g_kh + ((size_t)b * HWDIM + t + 8) * CDIM + (o - 128)) =
                    __floats2half2_rn(v2, v3);
            } else {                  // V: [ch][t]
                __half* vv = g_vh + (size_t)b * CDIM * HWDIM;
                vv[(size_t)(o - 256) * HWDIM + t]     = __float2half(v0);
                vv[(size_t)(o - 255) * HWDIM + t]     = __float2half(v1);
                vv[(size_t)(o - 256) * HWDIM + t + 8] = __float2half(v2);
                vv[(size_t)(o - 255) * HWDIM + t + 8] = __float2half(v3);
            }
        }
    }
}

// ---------------------------------------------------------------------------
// 4. Flash attention: fp16 mma, register-resident P, direct cp.async staging,
//    64-key tiles processed in TWO 32-key halves to keep live regs < 128
//    (R11 spilled at the full-tile liveness).
//    256 threads, 8 warps x 32 q = 256 q/CTA, double buffer, 16KB smem.
// ---------------------------------------------------------------------------
#define NT (HWDIM / 64)

__global__ void __launch_bounds__(256, 2) attn_mma_kernel() {
    __shared__ __align__(16) char smem[16384];
    uint32_t smem_u;
    asm("{ .reg .u64 t; cvta.to.shared.u64 t, %1; cvt.u32.u64 %0, t; }"
        : "=r"(smem_u) : "l"(smem));

    const int b = blockIdx.z, h = blockIdx.y;
    const int q0 = blockIdx.x * 256;
    const int tid = threadIdx.x;
    const int warp = tid >> 5, lane = tid & 31;
    const int lr = lane >> 2, lc = lane & 3;
    const int r8 = lane & 7, j8 = lane >> 3;
    const int qbase = warp * 32;

    const __half* Qh = g_qh + (size_t)b * HWDIM * CDIM;
    const __half* Kh = g_kh + (size_t)b * HWDIM * CDIM;
    const __half* Vh = g_vh + ((size_t)b * CDIM + h * HD) * HWDIM;

    // tile-load indices: 1 K chunk + 1 V chunk per thread
    const int lk_key = tid >> 2, lk_g = tid & 3;   // K: row=key(64), 4x16B chunks
    const int lv_ch  = tid >> 3, lv_g = tid & 7;   // V: row=ch(32), 8x16B chunks

    // ---- stage tile 0 into buf 0 ----
    cpa16(smem_u + lk_key * 64 + ((lk_g ^ ((lk_key >> 1) & 3)) << 4),
          Kh + (size_t)lk_key * CDIM + h * HD + lk_g * 8);
    cpa16(smem_u + 8192 + lv_ch * 128 + ((lv_g ^ (lv_ch & 7)) << 4),
          Vh + (size_t)lv_ch * HWDIM + lv_g * 8);
    asm volatile("cp.async.commit_group;" ::: "memory");

    // ---- Q fragments (fp16 pre-scaled) ----
    uint32_t qa[2][2][4];
#pragma unroll
    for (int mf = 0; mf < 2; mf++) {
        int qrow = q0 + qbase + mf * 16 + lr;
#pragma unroll
        for (int ks = 0; ks < 2; ks++) {
            int cc = h * HD + 2 * lc + 16 * ks;
            qa[mf][ks][0] = *(const uint32_t*)(Qh + (size_t)qrow * CDIM + cc);
            qa[mf][ks][1] = *(const uint32_t*)(Qh + (size_t)(qrow + 8) * CDIM + cc);
            qa[mf][ks][2] = *(const uint32_t*)(Qh + (size_t)qrow * CDIM + cc + 8);
            qa[mf][ks][3] = *(const uint32_t*)(Qh + (size_t)(qrow + 8) * CDIM + cc + 8);
        }
    }

    float l_i[2][2] = {{0.f, 0.f}, {0.f, 0.f}};
    float oacc[2][4][4];
#pragma unroll
    for (int mf = 0; mf < 2; mf++)
#pragma unroll
        for (int nf = 0; nf < 4; nf++)
#pragma unroll
            for (int c = 0; c < 4; c++) oacc[mf][nf][c] = 0.f;

    for (int t = 0; t < NT; t++) {
        // ---- stage tile t+1 into the other buffer ----
        if (t < NT - 1) {
            const int j0n = (t + 1) * 64;
            const int nb = (t + 1) & 1;
            cpa16(smem_u + nb * 4096 + lk_key * 64 + ((lk_g ^ ((lk_key >> 1) & 3)) << 4),
                  Kh + (size_t)(j0n + lk_key) * CDIM + h * HD + lk_g * 8);
            cpa16(smem_u + 8192 + nb * 4096 + lv_ch * 128 + ((lv_g ^ (lv_ch & 7)) << 4),
                  Vh + (size_t)lv_ch * HWDIM + j0n + lv_g * 8);
            asm volatile("cp.async.commit_group;" ::: "memory");
            asm volatile("cp.async.wait_group 1;" ::: "memory");
        } else {
            asm volatile("cp.async.wait_group 0;" ::: "memory");
        }
        __syncthreads();  // tile t visible to all threads

        const uint32_t kfb = smem_u + (t & 1) * 4096;
        const uint32_t vfb = smem_u + 8192 + (t & 1) * 4096;

        // ==== process tile in two 32-key halves (bounded liveness) ====
#pragma unroll
        for (int hh2 = 0; hh2 < 2; hh2++) {
            // ---- S = Q @ K^T for keys [32*hh2, 32*hh2+32) ----
            float sacc[2][4][4];
#pragma unroll
            for (int mf = 0; mf < 2; mf++)
#pragma unroll
                for (int nfl = 0; nfl < 4; nfl++)
#pragma unroll
                    for (int c = 0; c < 4; c++) sacc[mf][nfl][c] = 0.f;

#pragma unroll
            for (int nfl = 0; nfl < 4; nfl++) {
                uint32_t kb[4];
                int row = hh2 * 32 + nfl * 8 + r8;
                ldm4(kb, kfb + row * 64 + ((j8 ^ ((row >> 1) & 3)) << 4));
#pragma unroll
                for (int mf = 0; mf < 2; mf++) {
                    mma16(sacc[mf][nfl], qa[mf][0], kb[0], kb[1]);
                    mma16(sacc[mf][nfl], qa[mf][1], kb[2], kb[3]);
                }
            }

            // ---- exp2 -> fp16 P (registers), row sums ----
            uint32_t ph[2][2][4];
#pragma unroll
            for (int mf = 0; mf < 2; mf++) {
#pragma unroll
                for (int nfl = 0; nfl < 4; nfl++) {
                    ph[mf][0][nfl] = h2ex2(packh2(sacc[mf][nfl][0], sacc[mf][nfl][1]));
                    ph[mf][1][nfl] = h2ex2(packh2(sacc[mf][nfl][2], sacc[mf][nfl][3]));
                }
#pragma unroll
                for (int ri = 0; ri < 2; ri++) {
                    const uint32_t* p = ph[mf][ri];
                    __half2 s0 = __hadd2(*(__half2*)&p[0], *(__half2*)&p[1]);
                    __half2 s1 = __hadd2(*(__half2*)&p[2], *(__half2*)&p[3]);
                    __half2 s = __hadd2(s0, s1);
                    float2 f = __half22float2(s);
                    float sum = f.x + f.y;
                    sum += __shfl_xor_sync(0xffffffffu, sum, 1);
                    sum += __shfl_xor_sync(0xffffffffu, sum, 2);
                    l_i[mf][ri] += sum;
                }
            }

            // ---- V b-frags for this key half ----
            uint32_t vbl[4][4];
#pragma unroll
            for (int nf = 0; nf < 4; nf++) {
                int row = nf * 8 + r8;
                int g = hh2 * 4 + j8;
                ldm4(vbl[nf], vfb + row * 128 + ((g ^ r8) << 4));
            }

            // ---- O += P @ V (A-frags direct from ph registers) ----
#pragma unroll
            for (int mf = 0; mf < 2; mf++) {
#pragma unroll
                for (int kql = 0; kql < 2; kql++) {
                    uint32_t pa[4] = {ph[mf][0][2 * kql], ph[mf][1][2 * kql],
                                      ph[mf][0][2 * kql + 1], ph[mf][1][2 * kql + 1]};
#pragma unroll
                    for (int nf = 0; nf < 4; nf++)
                        mma16(oacc[mf][nf], pa, vbl[nf][2 * kql], vbl[nf][2 * kql + 1]);
                }
            }
        }
        __syncthreads();  // all reads of buf t&1 done before it is re-staged
    }

    // ---- epilogue: fp16 [t][c] output ----
#pragma unroll
    for (int mf = 0; mf < 2; mf++)
#pragma unroll
        for (int ri = 0; ri < 2; ri++) {
            float inv = 1.f / l_i[mf][ri];
            int q = q0 + qbase + mf * 16 + lr + 8 * ri;
#pragma unroll
            for (int nf = 0; nf < 4; nf++) {
                int ch = h * HD + nf * 8 + 2 * lc;
                *(uint32_t*)(g_atth + ((size_t)b * HWDIM + q) * CDIM + ch) =
                    packh2(oacc[mf][nf][2 * ri] * inv, oacc[mf][nf][2 * ri + 1] * inv);
            }
        }
}

// ---------------------------------------------------------------------------
// 5. Projection GEMM, fp16 tensor cores + fp32 bias/residual epilogue.
// ---------------------------------------------------------------------------
#define PROJ_SMEM (16384 + 32768)

__global__ void __launch_bounds__(256) proj_h_kernel(const float* __restrict__ W,
                                                     const float* __restrict__ bias,
                                                     float* __restrict__ Out) {
    extern __shared__ char qs[];
    uint32_t ws_u, as_u;
    asm("{ .reg .u64 t; cvta.to.shared.u64 t, %1; cvt.u32.u64 %0, t; }"
        : "=r"(ws_u) : "l"(qs));
    as_u = ws_u + 16384;

    const int b = blockIdx.z;
    const int ob0 = blockIdx.y * 64;
    const int t0 = blockIdx.x * 128;
    const int tid = threadIdx.x, warp = tid >> 5, lane = tid & 31;
    const int lr = lane >> 2, lc = lane & 3, r8 = lane & 7, j8 = lane >> 3;

    // ---- W tile ----
    {
        int row = tid >> 2;
#pragma unroll
        for (int i = 0; i < 4; i++) {
            int g = (tid & 3) * 4 + i;
            const float* wp = W + (size_t)(ob0 + row) * CDIM + g * 8;
            float4 wa = *(const float4*)wp;
            float4 wb = *(const float4*)(wp + 4);
            sts128u(ws_u + row * 256 + ((g ^ (row & 7)) << 4),
                    packh2(wa.x, wa.y), packh2(wa.z, wa.w),
                    packh2(wb.x, wb.y), packh2(wb.z, wb.w));
        }
    }
    // ---- A tile: [128 t][128 c] fp16 via cp.async ----
    {
        int tg = tid & 15, row0 = tid >> 4;
        const __half* ap = g_atth + (size_t)b * HWDIM * CDIM;
#pragma unroll
        for (int j = 0; j < 8; j++) {
            int row = row0 + 16 * j;
            cpa16(as_u + row * 256 + ((tg ^ (row & 7)) << 4),
                  ap + (size_t)(t0 + row) * CDIM + tg * 8);
        }
        asm volatile("cp.async.commit_group;" ::: "memory");
    }
    asm volatile("cp.async.wait_group 0;" ::: "memory");
    __syncthreads();

    const int wm = warp & 1, wn = warp >> 1;
    float acc[4][2][4];
#pragma unroll
    for (int mi = 0; mi < 4; mi++)
#pragma unroll
        for (int n8 = 0; n8 < 2; n8++)
#pragma unroll
            for (int c = 0; c < 4; c++) acc[mi][n8][c] = 0.f;

#pragma unroll
    for (int ks = 0; ks < 4; ks++) {
        uint32_t bf[2][4];
#pragma unroll
        for (int n8 = 0; n8 < 2; n8++) {
            int row = wn * 16 + n8 * 8 + r8;
            ldm4(bf[n8], ws_u + row * 256 + (((ks * 4 + j8) ^ (row & 7)) << 4));
        }
        uint32_t af[4][2][4];
#pragma unroll
        for (int mi = 0; mi < 4; mi++)
#pragma unroll
            for (int kh = 0; kh < 2; kh++) {
                int row = wm * 64 + mi * 16 + ((j8 & 1) << 3) + r8;
                int g = ks * 4 + kh * 2 + (j8 >> 1);
                ldm4(af[mi][kh], as_u + row * 256 + ((g ^ (row & 7)) << 4));
            }
#pragma unroll
        for (int mi = 0; mi < 4; mi++)
#pragma unroll
            for (int n8 = 0; n8 < 2; n8++) {
                mma16(acc[mi][n8], af[mi][0], bf[n8][0], bf[n8][1]);
                mma16(acc[mi][n8], af[mi][1], bf[n8][2], bf[n8][3]);
            }
    }

    // ---- epilogue: fp32 + bias + residual ----
#pragma unroll
    for (int mi = 0; mi < 4; mi++) {
        int t = t0 + wm * 64 + mi * 16 + lr;
#pragma unroll
        for (int n8 = 0; n8 < 2; n8++) {
            int o = ob0 + wn * 16 + n8 * 8 + 2 * lc;
            float b0 = bias[o], b1 = bias[o + 1];
            size_t i00 = ((size_t)b * CDIM + o) * HWDIM + t;
            size_t i10 = i00 + HWDIM;
            Out[i00]     = acc[mi][n8][0] + b0 + g_xn[i00];
            Out[i10]     = acc[mi][n8][1] + b1 + g_xn[i10];
            Out[i00 + 8] = acc[mi][n8][2] + b0 + g_xn[i00 + 8];
            Out[i10 + 8] = acc[mi][n8][3] + b1 + g_xn[i10 + 8];
        }
    }
}

// ---------------------------------------------------------------------------
// Launch
// ---------------------------------------------------------------------------
extern "C" void kernel_launch(void* const* d_in, const int* in_sizes, int n_in,
                              void* d_out, int out_size) {
    const float* x      = (const float*)d_in[0];
    const float* gn_w   = (const float*)d_in[1];
    const float* gn_b   = (const float*)d_in[2];
    const float* qkv_w  = (const float*)d_in[3];
    const float* qkv_b  = (const float*)d_in[4];
    const float* proj_w = (const float*)d_in[5];
    const float* proj_b = (const float*)d_in[6];
    float* out = (float*)d_out;

    static bool attr_set = false;
    if (!attr_set) {
        cudaFuncSetAttribute(qkv_h_kernel,
                             cudaFuncAttributeMaxDynamicSharedMemorySize, QKV_SMEM);
        cudaFuncSetAttribute(proj_h_kernel,
                             cudaFuncAttributeMaxDynamicSharedMemorySize, PROJ_SMEM);
        attr_set = true;
    }

    gn_stats_kernel<<<BATCH * NGROUP, 256>>>(x);
    gn_apply_kernel<<<(BATCH * CDIM * HWDIM / 4 + 255) / 256, 256>>>(x, gn_w, gn_b);
    qkv_h_kernel<<<dim3(HWDIM / 128, OC / 64, BATCH), 256, QKV_SMEM>>>(qkv_w, qkv_b);
    attn_mma_kernel<<<dim3(HWDIM / 256, NH, BATCH), 256>>>();
    proj_h_kernel<<<dim3(HWDIM / 128, CDIM / 64, BATCH), 256, PROJ_SMEM>>>(
        proj_w, proj_b, out);
}

// round 14
// speedup vs baseline: 1.5668x; 1.0387x over previous
#include <cuda_runtime.h>
#include <cuda_fp16.h>
#include <stdint.h>
#include <math.h>

#define BATCH 4
#define CDIM 128
#define HWDIM 4096
#define NGROUP 8
#define CPG 16
#define NH 4
#define HD 32
#define OC 384   // 3*C

// Scratch (allocation-free: device globals)
__device__ __align__(16) __half g_xnh[BATCH * CDIM * HWDIM];     // fp16 [b][c][t]
__device__ __align__(16) __half g_qh[BATCH * HWDIM * CDIM];      // fp16 [b][t][128], pre-scaled Q
__device__ __align__(16) __half g_kh[BATCH * HWDIM * CDIM];      // fp16 [b][t][128] K
__device__ __align__(16) __half g_vh[BATCH * CDIM * HWDIM];      // fp16 [b][ch][t]  V
__device__ __align__(16) __half g_atth[BATCH * HWDIM * CDIM];    // fp16 [b][t][c] attn out
__device__ float g_mean[BATCH * NGROUP];
__device__ float g_rstd[BATCH * NGROUP];

__device__ __forceinline__ void mma16(float* d, const uint32_t* a, uint32_t b0, uint32_t b1) {
    asm volatile(
        "mma.sync.aligned.m16n8k16.row.col.f32.f16.f16.f32 "
        "{%0,%1,%2,%3},{%4,%5,%6,%7},{%8,%9},{%0,%1,%2,%3};\n"
        : "+f"(d[0]), "+f"(d[1]), "+f"(d[2]), "+f"(d[3])
        : "r"(a[0]), "r"(a[1]), "r"(a[2]), "r"(a[3]), "r"(b0), "r"(b1));
}

__device__ __forceinline__ void ldm4(uint32_t* r, uint32_t addr) {
    asm volatile("ldmatrix.sync.aligned.m8n8.x4.shared.b16 {%0,%1,%2,%3}, [%4];"
                 : "=r"(r[0]), "=r"(r[1]), "=r"(r[2]), "=r"(r[3]) : "r"(addr));
}

__device__ __forceinline__ void ldm4t(uint32_t* r, uint32_t addr) {
    asm volatile("ldmatrix.sync.aligned.m8n8.x4.trans.shared.b16 {%0,%1,%2,%3}, [%4];"
                 : "=r"(r[0]), "=r"(r[1]), "=r"(r[2]), "=r"(r[3]) : "r"(addr));
}

__device__ __forceinline__ uint32_t packh2(float lo, float hi) {
    __half2 h = __floats2half2_rn(lo, hi);
    return *reinterpret_cast<uint32_t*>(&h);
}

__device__ __forceinline__ uint32_t h2ex2(uint32_t x) {
    uint32_t r;
    asm("ex2.approx.f16x2 %0, %1;" : "=r"(r) : "r"(x));
    return r;
}

__device__ __forceinline__ void cpa16(uint32_t dst, const void* src) {
    asm volatile("cp.async.cg.shared.global [%0], [%1], 16;" :: "r"(dst), "l"(src));
}

__device__ __forceinline__ void sts128u(uint32_t addr, uint32_t a, uint32_t b,
                                        uint32_t c, uint32_t d) {
    asm volatile("st.shared.v4.u32 [%0], {%1,%2,%3,%4};"
                 :: "r"(addr), "r"(a), "r"(b), "r"(c), "r"(d));
}

// ---------------------------------------------------------------------------
// 1. GroupNorm statistics
// ---------------------------------------------------------------------------
__global__ void gn_stats_kernel(const float* __restrict__ x) {
    int bg = blockIdx.x;
    const float4* p = reinterpret_cast<const float4*>(x + (size_t)bg * CPG * HWDIM);
    const int n4 = CPG * HWDIM / 4;
    float s = 0.f, ss = 0.f;
    for (int i = threadIdx.x; i < n4; i += blockDim.x) {
        float4 v = p[i];
        s  += v.x + v.y + v.z + v.w;
        ss += v.x * v.x + v.y * v.y + v.z * v.z + v.w * v.w;
    }
    __shared__ float sh_s[256], sh_ss[256];
    sh_s[threadIdx.x] = s;
    sh_ss[threadIdx.x] = ss;
    __syncthreads();
    for (int off = 128; off > 0; off >>= 1) {
        if (threadIdx.x < off) {
            sh_s[threadIdx.x]  += sh_s[threadIdx.x + off];
            sh_ss[threadIdx.x] += sh_ss[threadIdx.x + off];
        }
        __syncthreads();
    }
    if (threadIdx.x == 0) {
        const float inv = 1.0f / (float)(CPG * HWDIM);
        float mean = sh_s[0] * inv;
        float var  = sh_ss[0] * inv - mean * mean;
        g_mean[bg] = mean;
        g_rstd[bg] = rsqrtf(var + 1e-5f);
    }
}

// ---------------------------------------------------------------------------
// 2. Apply GroupNorm: fp16 out only (residual recomputed in proj epilogue)
// ---------------------------------------------------------------------------
__global__ void gn_apply_kernel(const float* __restrict__ x,
                                const float* __restrict__ w,
                                const float* __restrict__ bias) {
    int i4 = blockIdx.x * blockDim.x + threadIdx.x;
    const int total4 = BATCH * CDIM * HWDIM / 4;
    if (i4 >= total4) return;
    int e  = i4 * 4;
    int c  = (e / HWDIM) % CDIM;
    int bg = e / (CPG * HWDIM);
    float mean = g_mean[bg], rstd = g_rstd[bg];
    float sw = w[c] * rstd;
    float sb = bias[c] - mean * sw;
    float4 v = reinterpret_cast<const float4*>(x)[i4];
    reinterpret_cast<__half2*>(g_xnh)[i4 * 2] =
        __floats2half2_rn(v.x * sw + sb, v.y * sw + sb);
    reinterpret_cast<__half2*>(g_xnh)[i4 * 2 + 1] =
        __floats2half2_rn(v.z * sw + sb, v.w * sw + sb);
}

// ---------------------------------------------------------------------------
// 3. QKV GEMM, fp16 tensor cores. Out = W @ xn + bias.
//    Q -> g_qh[t][o] pre-scaled; K -> g_kh[t][o-128]; V -> g_vh[o-256][t].
// ---------------------------------------------------------------------------
#define QKV_SMEM (16384 + 32768)

__global__ void __launch_bounds__(256) qkv_h_kernel(const float* __restrict__ W,
                                                    const float* __restrict__ bias) {
    extern __shared__ char qs[];
    uint32_t ws_u, xs_u;
    asm("{ .reg .u64 t; cvta.to.shared.u64 t, %1; cvt.u32.u64 %0, t; }"
        : "=r"(ws_u) : "l"(qs));
    xs_u = ws_u + 16384;

    const int b = blockIdx.z;
    const int ob0 = blockIdx.y * 64;
    const int t0 = blockIdx.x * 128;
    const int tid = threadIdx.x, warp = tid >> 5, lane = tid & 31;
    const int lr = lane >> 2, lc = lane & 3, r8 = lane & 7, j8 = lane >> 3;

    // ---- W tile: [64 o][128 c] fp32 -> fp16, swizzled ----
    {
        int row = tid >> 2;
#pragma unroll
        for (int i = 0; i < 4; i++) {
            int g = (tid & 3) * 4 + i;
            const float* wp = W + (size_t)(ob0 + row) * CDIM + g * 8;
            float4 wa = *(const float4*)wp;
            float4 wb = *(const float4*)(wp + 4);
            sts128u(ws_u + row * 256 + ((g ^ (row & 7)) << 4),
                    packh2(wa.x, wa.y), packh2(wa.z, wa.w),
                    packh2(wb.x, wb.y), packh2(wb.z, wb.w));
        }
    }
    // ---- X tile: [128 c][128 t] fp16 via cp.async ----
    {
        int tg = tid & 15, c0 = (tid >> 4) * 8;
        const __half* xp = g_xnh + (size_t)b * CDIM * HWDIM;
#pragma unroll
        for (int j = 0; j < 8; j++) {
            int c = c0 + j;
            cpa16(xs_u + c * 256 + ((tg ^ (c & 7)) << 4),
                  xp + (size_t)c * HWDIM + t0 + tg * 8);
        }
        asm volatile("cp.async.commit_group;" ::: "memory");
    }
    asm volatile("cp.async.wait_group 0;" ::: "memory");
    __syncthreads();

    const int wm = warp & 1, wn = warp >> 1;
    float acc[4][2][4];
#pragma unroll
    for (int mi = 0; mi < 4; mi++)
#pragma unroll
        for (int n8 = 0; n8 < 2; n8++)
#pragma unroll
            for (int c = 0; c < 4; c++) acc[mi][n8][c] = 0.f;

#pragma unroll
    for (int ks = 0; ks < 4; ks++) {
        uint32_t bf[2][4];
#pragma unroll
        for (int n8 = 0; n8 < 2; n8++) {
            int row = wn * 16 + n8 * 8 + r8;
            ldm4(bf[n8], ws_u + row * 256 + (((ks * 4 + j8) ^ (row & 7)) << 4));
        }
        uint32_t af[4][2][4];
#pragma unroll
        for (int mi = 0; mi < 4; mi++)
#pragma unroll
            for (int kh = 0; kh < 2; kh++) {
                int c_row = ks * 32 + kh * 16 + (lane & 7) + ((lane >> 4) & 1) * 8;
                int tg = wm * 8 + mi * 2 + ((lane >> 3) & 1);
                ldm4t(af[mi][kh], xs_u + c_row * 256 + ((tg ^ (c_row & 7)) << 4));
            }
#pragma unroll
        for (int mi = 0; mi < 4; mi++)
#pragma unroll
            for (int n8 = 0; n8 < 2; n8++) {
                mma16(acc[mi][n8], af[mi][0], bf[n8][0], bf[n8][1]);
                mma16(acc[mi][n8], af[mi][1], bf[n8][2], bf[n8][3]);
            }
    }

    // ---- epilogue ----
    const float QSC = 0.088388347648318447f * 1.4426950408889634f;  // C^-0.5 * log2(e)
#pragma unroll
    for (int mi = 0; mi < 4; mi++) {
        int t = t0 + wm * 64 + mi * 16 + lr;
#pragma unroll
        for (int n8 = 0; n8 < 2; n8++) {
            int o = ob0 + wn * 16 + n8 * 8 + 2 * lc;
            float b0 = bias[o], b1 = bias[o + 1];
            float v0 = acc[mi][n8][0] + b0, v1 = acc[mi][n8][1] + b1;
            float v2 = acc[mi][n8][2] + b0, v3 = acc[mi][n8][3] + b1;
            if (ob0 < 128) {          // Q: [t][o], pre-scaled
                *(__half2*)(g_qh + ((size_t)b * HWDIM + t) * CDIM + o) =
                    __floats2half2_rn(v0 * QSC, v1 * QSC);
                *(__half2*)(g_qh + ((size_t)b * HWDIM + t + 8) * CDIM + o) =
                    __floats2half2_rn(v2 * QSC, v3 * QSC);
            } else if (ob0 < 256) {   // K: [t][o-128]
                *(__half2*)(g_kh + ((size_t)b * HWDIM + t) * CDIM + (o - 128)) =
                    __floats2half2_rn(v0, v1);
                *(__half2*)(g_kh + ((size_t)b * HWDIM + t + 8) * CDIM + (o - 128)) =
                    __floats2half2_rn(v2, v3);
            } else {                  // V: [ch][t]
                __half* vv = g_vh + (size_t)b * CDIM * HWDIM;
                vv[(size_t)(o - 256) * HWDIM + t]     = __float2half(v0);
                vv[(size_t)(o - 255) * HWDIM + t]     = __float2half(v1);
                vv[(size_t)(o - 256) * HWDIM + t + 8] = __float2half(v2);
                vv[(size_t)(o - 255) * HWDIM + t + 8] = __float2half(v3);
            }
        }
    }
}

// ---------------------------------------------------------------------------
// 4. Flash attention: fp16 mma, register-resident P, direct cp.async staging.
//    128-key tiles (4 x 32-key halves, bounded liveness), double buffer.
//    256 threads, 8 warps x 32 q = 256 q/CTA, 32KB smem.
//    smem: kf[2][128 rows][64B] @0, vf[2][32 rows][256B] @16384.
// ---------------------------------------------------------------------------
#define NT (HWDIM / 128)   // 32 tiles

__global__ void __launch_bounds__(256, 2) attn_mma_kernel() {
    __shared__ __align__(16) char smem[32768];
    uint32_t smem_u;
    asm("{ .reg .u64 t; cvta.to.shared.u64 t, %1; cvt.u32.u64 %0, t; }"
        : "=r"(smem_u) : "l"(smem));

    const int b = blockIdx.z, h = blockIdx.y;
    const int q0 = blockIdx.x * 256;
    const int tid = threadIdx.x;
    const int warp = tid >> 5, lane = tid & 31;
    const int lr = lane >> 2, lc = lane & 3;
    const int r8 = lane & 7, j8 = lane >> 3;
    const int qbase = warp * 32;

    const __half* Qh = g_qh + (size_t)b * HWDIM * CDIM;
    const __half* Kh = g_kh + (size_t)b * HWDIM * CDIM;
    const __half* Vh = g_vh + ((size_t)b * CDIM + h * HD) * HWDIM;

    // tile-load indices: 2 K chunks + 2 V chunks per thread per 128-key tile
    const int lk_key = tid >> 1, lk_g0 = (tid & 1) * 2;   // K: row=key(128), 4x16B/row
    const int lv_ch  = tid >> 3, lv_g0 = tid & 7;         // V: row=ch(32), 16x16B/row

    // ---- stage tile 0 into buf 0 ----
#pragma unroll
    for (int i = 0; i < 2; i++) {
        int kg = lk_g0 + i;
        cpa16(smem_u + lk_key * 64 + ((kg ^ ((lk_key >> 1) & 3)) << 4),
              Kh + (size_t)lk_key * CDIM + h * HD + kg * 8);
        int vg = lv_g0 + i * 8;
        cpa16(smem_u + 16384 + lv_ch * 256 + ((vg ^ (lv_ch & 7)) << 4),
              Vh + (size_t)lv_ch * HWDIM + vg * 8);
    }
    asm volatile("cp.async.commit_group;" ::: "memory");

    // ---- Q fragments (fp16 pre-scaled) ----
    uint32_t qa[2][2][4];
#pragma unroll
    for (int mf = 0; mf < 2; mf++) {
        int qrow = q0 + qbase + mf * 16 + lr;
#pragma unroll
        for (int ks = 0; ks < 2; ks++) {
            int cc = h * HD + 2 * lc + 16 * ks;
            qa[mf][ks][0] = *(const uint32_t*)(Qh + (size_t)qrow * CDIM + cc);
            qa[mf][ks][1] = *(const uint32_t*)(Qh + (size_t)(qrow + 8) * CDIM + cc);
            qa[mf][ks][2] = *(const uint32_t*)(Qh + (size_t)qrow * CDIM + cc + 8);
            qa[mf][ks][3] = *(const uint32_t*)(Qh + (size_t)(qrow + 8) * CDIM + cc + 8);
        }
    }

    float l_i[2][2] = {{0.f, 0.f}, {0.f, 0.f}};
    float oacc[2][4][4];
#pragma unroll
    for (int mf = 0; mf < 2; mf++)
#pragma unroll
        for (int nf = 0; nf < 4; nf++)
#pragma unroll
            for (int c = 0; c < 4; c++) oacc[mf][nf][c] = 0.f;

    for (int t = 0; t < NT; t++) {
        // ---- stage tile t+1 into the other buffer ----
        if (t < NT - 1) {
            const int j0n = (t + 1) * 128;
            const int nb = (t + 1) & 1;
#pragma unroll
            for (int i = 0; i < 2; i++) {
                int kg = lk_g0 + i;
                cpa16(smem_u + nb * 8192 + lk_key * 64 + ((kg ^ ((lk_key >> 1) & 3)) << 4),
                      Kh + (size_t)(j0n + lk_key) * CDIM + h * HD + kg * 8);
                int vg = lv_g0 + i * 8;
                cpa16(smem_u + 16384 + nb * 8192 + lv_ch * 256 + ((vg ^ (lv_ch & 7)) << 4),
                      Vh + (size_t)lv_ch * HWDIM + j0n + vg * 8);
            }
            asm volatile("cp.async.commit_group;" ::: "memory");
            asm volatile("cp.async.wait_group 1;" ::: "memory");
        } else {
            asm volatile("cp.async.wait_group 0;" ::: "memory");
        }
        __syncthreads();  // tile t visible to all threads

        const uint32_t kfb = smem_u + (t & 1) * 8192;
        const uint32_t vfb = smem_u + 16384 + (t & 1) * 8192;

        // ==== process tile in four 32-key halves (bounded liveness) ====
#pragma unroll
        for (int hh2 = 0; hh2 < 4; hh2++) {
            // ---- S = Q @ K^T for keys [32*hh2, 32*hh2+32) ----
            float sacc[2][4][4];
#pragma unroll
            for (int mf = 0; mf < 2; mf++)
#pragma unroll
                for (int nfl = 0; nfl < 4; nfl++)
#pragma unroll
                    for (int c = 0; c < 4; c++) sacc[mf][nfl][c] = 0.f;

#pragma unroll
            for (int nfl = 0; nfl < 4; nfl++) {
                uint32_t kb[4];
                int row = hh2 * 32 + nfl * 8 + r8;
                ldm4(kb, kfb + row * 64 + ((j8 ^ ((row >> 1) & 3)) << 4));
#pragma unroll
                for (int mf = 0; mf < 2; mf++) {
                    mma16(sacc[mf][nfl], qa[mf][0], kb[0], kb[1]);
                    mma16(sacc[mf][nfl], qa[mf][1], kb[2], kb[3]);
                }
            }

            // ---- exp2 -> fp16 P (registers), row sums ----
            uint32_t ph[2][2][4];
#pragma unroll
            for (int mf = 0; mf < 2; mf++) {
#pragma unroll
                for (int nfl = 0; nfl < 4; nfl++) {
                    ph[mf][0][nfl] = h2ex2(packh2(sacc[mf][nfl][0], sacc[mf][nfl][1]));
                    ph[mf][1][nfl] = h2ex2(packh2(sacc[mf][nfl][2], sacc[mf][nfl][3]));
                }
#pragma unroll
                for (int ri = 0; ri < 2; ri++) {
                    const uint32_t* p = ph[mf][ri];
                    __half2 s0 = __hadd2(*(__half2*)&p[0], *(__half2*)&p[1]);
                    __half2 s1 = __hadd2(*(__half2*)&p[2], *(__half2*)&p[3]);
                    __half2 s = __hadd2(s0, s1);
                    float2 f = __half22float2(s);
                    float sum = f.x + f.y;
                    sum += __shfl_xor_sync(0xffffffffu, sum, 1);
                    sum += __shfl_xor_sync(0xffffffffu, sum, 2);
                    l_i[mf][ri] += sum;
                }
            }

            // ---- V b-frags for this key half ----
            uint32_t vbl[4][4];
#pragma unroll
            for (int nf = 0; nf < 4; nf++) {
                int row = nf * 8 + r8;
                int g = hh2 * 4 + j8;
                ldm4(vbl[nf], vfb + row * 256 + ((g ^ (row & 7)) << 4));
            }

            // ---- O += P @ V (A-frags direct from ph registers) ----
#pragma unroll
            for (int mf = 0; mf < 2; mf++) {
#pragma unroll
                for (int kql = 0; kql < 2; kql++) {
                    uint32_t pa[4] = {ph[mf][0][2 * kql], ph[mf][1][2 * kql],
                                      ph[mf][0][2 * kql + 1], ph[mf][1][2 * kql + 1]};
#pragma unroll
                    for (int nf = 0; nf < 4; nf++)
                        mma16(oacc[mf][nf], pa, vbl[nf][2 * kql], vbl[nf][2 * kql + 1]);
                }
            }
        }
        __syncthreads();  // all reads of buf t&1 done before it is re-staged
    }

    // ---- epilogue: fp16 [t][c] output ----
#pragma unroll
    for (int mf = 0; mf < 2; mf++)
#pragma unroll
        for (int ri = 0; ri < 2; ri++) {
            float inv = 1.f / l_i[mf][ri];
            int q = q0 + qbase + mf * 16 + lr + 8 * ri;
#pragma unroll
            for (int nf = 0; nf < 4; nf++) {
                int ch = h * HD + nf * 8 + 2 * lc;
                *(uint32_t*)(g_atth + ((size_t)b * HWDIM + q) * CDIM + ch) =
                    packh2(oacc[mf][nf][2 * ri] * inv, oacc[mf][nf][2 * ri + 1] * inv);
            }
        }
}

// ---------------------------------------------------------------------------
// 5. Projection GEMM, fp16 tensor cores; epilogue adds bias + recomputed
//    GroupNorm residual (from x, mean, rstd, w, b) in fp32.
// ---------------------------------------------------------------------------
#define PROJ_SMEM (16384 + 32768)

__global__ void __launch_bounds__(256) proj_h_kernel(const float* __restrict__ W,
                                                     const float* __restrict__ bias,
                                                     float* __restrict__ Out,
                                                     const float* __restrict__ x,
                                                     const float* __restrict__ gnw,
                                                     const float* __restrict__ gnb) {
    extern __shared__ char qs[];
    uint32_t ws_u, as_u;
    asm("{ .reg .u64 t; cvta.to.shared.u64 t, %1; cvt.u32.u64 %0, t; }"
        : "=r"(ws_u) : "l"(qs));
    as_u = ws_u + 16384;

    const int b = blockIdx.z;
    const int ob0 = blockIdx.y * 64;
    const int t0 = blockIdx.x * 128;
    const int tid = threadIdx.x, warp = tid >> 5, lane = tid & 31;
    const int lr = lane >> 2, lc = lane & 3, r8 = lane & 7, j8 = lane >> 3;

    // ---- W tile ----
    {
        int row = tid >> 2;
#pragma unroll
        for (int i = 0; i < 4; i++) {
            int g = (tid & 3) * 4 + i;
            const float* wp = W + (size_t)(ob0 + row) * CDIM + g * 8;
            float4 wa = *(const float4*)wp;
            float4 wb = *(const float4*)(wp + 4);
            sts128u(ws_u + row * 256 + ((g ^ (row & 7)) << 4),
                    packh2(wa.x, wa.y), packh2(wa.z, wa.w),
                    packh2(wb.x, wb.y), packh2(wb.z, wb.w));
        }
    }
    // ---- A tile: [128 t][128 c] fp16 via cp.async ----
    {
        int tg = tid & 15, row0 = tid >> 4;
        const __half* ap = g_atth + (size_t)b * HWDIM * CDIM;
#pragma unroll
        for (int j = 0; j < 8; j++) {
            int row = row0 + 16 * j;
            cpa16(as_u + row * 256 + ((tg ^ (row & 7)) << 4),
                  ap + (size_t)(t0 + row) * CDIM + tg * 8);
        }
        asm volatile("cp.async.commit_group;" ::: "memory");
    }
    asm volatile("cp.async.wait_group 0;" ::: "memory");
    __syncthreads();

    const int wm = warp & 1, wn = warp >> 1;
    float acc[4][2][4];
#pragma unroll
    for (int mi = 0; mi < 4; mi++)
#pragma unroll
        for (int n8 = 0; n8 < 2; n8++)
#pragma unroll
            for (int c = 0; c < 4; c++) acc[mi][n8][c] = 0.f;

#pragma unroll
    for (int ks = 0; ks < 4; ks++) {
        uint32_t bf[2][4];
#pragma unroll
        for (int n8 = 0; n8 < 2; n8++) {
            int row = wn * 16 + n8 * 8 + r8;
            ldm4(bf[n8], ws_u + row * 256 + (((ks * 4 + j8) ^ (row & 7)) << 4));
        }
        uint32_t af[4][2][4];
#pragma unroll
        for (int mi = 0; mi < 4; mi++)
#pragma unroll
            for (int kh = 0; kh < 2; kh++) {
                int row = wm * 64 + mi * 16 + ((j8 & 1) << 3) + r8;
                int g = ks * 4 + kh * 2 + (j8 >> 1);
                ldm4(af[mi][kh], as_u + row * 256 + ((g ^ (row & 7)) << 4));
            }
#pragma unroll
        for (int mi = 0; mi < 4; mi++)
#pragma unroll
            for (int n8 = 0; n8 < 2; n8++) {
                mma16(acc[mi][n8], af[mi][0], bf[n8][0], bf[n8][1]);
                mma16(acc[mi][n8], af[mi][1], bf[n8][2], bf[n8][3]);
            }
    }

    // ---- epilogue: fp32 + bias + recomputed GN residual ----
#pragma unroll
    for (int mi = 0; mi < 4; mi++) {
        int t = t0 + wm * 64 + mi * 16 + lr;
#pragma unroll
        for (int n8 = 0; n8 < 2; n8++) {
            int o = ob0 + wn * 16 + n8 * 8 + 2 * lc;
            int bg = b * NGROUP + o / CPG;
            float mean = g_mean[bg], rstd = g_rstd[bg];
            float sw0 = gnw[o] * rstd,     sb0 = gnb[o] - mean * sw0;
            float sw1 = gnw[o + 1] * rstd, sb1 = gnb[o + 1] - mean * sw1;
            float b0 = bias[o], b1 = bias[o + 1];
            size_t i00 = ((size_t)b * CDIM + o) * HWDIM + t;
            size_t i10 = i00 + HWDIM;
            Out[i00]     = acc[mi][n8][0] + b0 + x[i00] * sw0 + sb0;
            Out[i10]     = acc[mi][n8][1] + b1 + x[i10] * sw1 + sb1;
            Out[i00 + 8] = acc[mi][n8][2] + b0 + x[i00 + 8] * sw0 + sb0;
            Out[i10 + 8] = acc[mi][n8][3] + b1 + x[i10 + 8] * sw1 + sb1;
        }
    }
}

// ---------------------------------------------------------------------------
// Launch
// ---------------------------------------------------------------------------
extern "C" void kernel_launch(void* const* d_in, const int* in_sizes, int n_in,
                              void* d_out, int out_size) {
    const float* x      = (const float*)d_in[0];
    const float* gn_w   = (const float*)d_in[1];
    const float* gn_b   = (const float*)d_in[2];
    const float* qkv_w  = (const float*)d_in[3];
    const float* qkv_b  = (const float*)d_in[4];
    const float* proj_w = (const float*)d_in[5];
    const float* proj_b = (const float*)d_in[6];
    float* out = (float*)d_out;

    static bool attr_set = false;
    if (!attr_set) {
        cudaFuncSetAttribute(qkv_h_kernel,
                             cudaFuncAttributeMaxDynamicSharedMemorySize, QKV_SMEM);
        cudaFuncSetAttribute(proj_h_kernel,
                             cudaFuncAttributeMaxDynamicSharedMemorySize, PROJ_SMEM);
        attr_set = true;
    }

    gn_stats_kernel<<<BATCH * NGROUP, 256>>>(x);
    gn_apply_kernel<<<(BATCH * CDIM * HWDIM / 4 + 255) / 256, 256>>>(x, gn_w, gn_b);
    qkv_h_kernel<<<dim3(HWDIM / 128, OC / 64, BATCH), 256, QKV_SMEM>>>(qkv_w, qkv_b);
    attn_mma_kernel<<<dim3(HWDIM / 256, NH, BATCH), 256>>>();
    proj_h_kernel<<<dim3(HWDIM / 128, CDIM / 64, BATCH), 256, PROJ_SMEM>>>(
        proj_w, proj_b, out, x, gn_w, gn_b);
}

// round 15
// speedup vs baseline: 1.6862x; 1.0762x over previous
#include <cuda_runtime.h>
#include <cuda_fp16.h>
#include <stdint.h>
#include <math.h>

#define BATCH 4
#define CDIM 128
#define HWDIM 4096
#define NGROUP 8
#define CPG 16
#define NH 4
#define HD 32
#define OC 384   // 3*C

// Scratch (allocation-free: device globals)
__device__ __align__(16) __half g_xnh[BATCH * CDIM * HWDIM];     // fp16 [b][c][t]
__device__ __align__(16) __half g_qh[BATCH * HWDIM * CDIM];      // fp16 [b][t][128], pre-scaled Q
__device__ __align__(16) __half g_kh[BATCH * HWDIM * CDIM];      // fp16 [b][t][128] K
__device__ __align__(16) __half g_vh[BATCH * CDIM * HWDIM];      // fp16 [b][ch][t]  V
__device__ __align__(16) __half g_atth[BATCH * HWDIM * CDIM];    // fp16 [b][t][c] attn out
__device__ float g_mean[BATCH * NGROUP];
__device__ float g_rstd[BATCH * NGROUP];

__device__ __forceinline__ void mma16(float* d, const uint32_t* a, uint32_t b0, uint32_t b1) {
    asm volatile(
        "mma.sync.aligned.m16n8k16.row.col.f32.f16.f16.f32 "
        "{%0,%1,%2,%3},{%4,%5,%6,%7},{%8,%9},{%0,%1,%2,%3};\n"
        : "+f"(d[0]), "+f"(d[1]), "+f"(d[2]), "+f"(d[3])
        : "r"(a[0]), "r"(a[1]), "r"(a[2]), "r"(a[3]), "r"(b0), "r"(b1));
}

__device__ __forceinline__ void ldm4(uint32_t* r, uint32_t addr) {
    asm volatile("ldmatrix.sync.aligned.m8n8.x4.shared.b16 {%0,%1,%2,%3}, [%4];"
                 : "=r"(r[0]), "=r"(r[1]), "=r"(r[2]), "=r"(r[3]) : "r"(addr));
}

__device__ __forceinline__ void ldm4t(uint32_t* r, uint32_t addr) {
    asm volatile("ldmatrix.sync.aligned.m8n8.x4.trans.shared.b16 {%0,%1,%2,%3}, [%4];"
                 : "=r"(r[0]), "=r"(r[1]), "=r"(r[2]), "=r"(r[3]) : "r"(addr));
}

__device__ __forceinline__ uint32_t packh2(float lo, float hi) {
    __half2 h = __floats2half2_rn(lo, hi);
    return *reinterpret_cast<uint32_t*>(&h);
}

__device__ __forceinline__ uint32_t h2ex2(uint32_t x) {
    uint32_t r;
    asm("ex2.approx.f16x2 %0, %1;" : "=r"(r) : "r"(x));
    return r;
}

__device__ __forceinline__ void cpa16(uint32_t dst, const void* src) {
    asm volatile("cp.async.cg.shared.global [%0], [%1], 16;" :: "r"(dst), "l"(src));
}

__device__ __forceinline__ void sts128u(uint32_t addr, uint32_t a, uint32_t b,
                                        uint32_t c, uint32_t d) {
    asm volatile("st.shared.v4.u32 [%0], {%1,%2,%3,%4};"
                 :: "r"(addr), "r"(a), "r"(b), "r"(c), "r"(d));
}

// ---------------------------------------------------------------------------
// 1. GroupNorm statistics
// ---------------------------------------------------------------------------
__global__ void gn_stats_kernel(const float* __restrict__ x) {
    int bg = blockIdx.x;
    const float4* p = reinterpret_cast<const float4*>(x + (size_t)bg * CPG * HWDIM);
    const int n4 = CPG * HWDIM / 4;
    float s = 0.f, ss = 0.f;
    for (int i = threadIdx.x; i < n4; i += blockDim.x) {
        float4 v = p[i];
        s  += v.x + v.y + v.z + v.w;
        ss += v.x * v.x + v.y * v.y + v.z * v.z + v.w * v.w;
    }
    __shared__ float sh_s[256], sh_ss[256];
    sh_s[threadIdx.x] = s;
    sh_ss[threadIdx.x] = ss;
    __syncthreads();
    for (int off = 128; off > 0; off >>= 1) {
        if (threadIdx.x < off) {
            sh_s[threadIdx.x]  += sh_s[threadIdx.x + off];
            sh_ss[threadIdx.x] += sh_ss[threadIdx.x + off];
        }
        __syncthreads();
    }
    if (threadIdx.x == 0) {
        const float inv = 1.0f / (float)(CPG * HWDIM);
        float mean = sh_s[0] * inv;
        float var  = sh_ss[0] * inv - mean * mean;
        g_mean[bg] = mean;
        g_rstd[bg] = rsqrtf(var + 1e-5f);
    }
}

// ---------------------------------------------------------------------------
// 2. Apply GroupNorm: fp16 out only (residual recomputed in proj epilogue)
// ---------------------------------------------------------------------------
__global__ void gn_apply_kernel(const float* __restrict__ x,
                                const float* __restrict__ w,
                                const float* __restrict__ bias) {
    int i4 = blockIdx.x * blockDim.x + threadIdx.x;
    const int total4 = BATCH * CDIM * HWDIM / 4;
    if (i4 >= total4) return;
    int e  = i4 * 4;
    int c  = (e / HWDIM) % CDIM;
    int bg = e / (CPG * HWDIM);
    float mean = g_mean[bg], rstd = g_rstd[bg];
    float sw = w[c] * rstd;
    float sb = bias[c] - mean * sw;
    float4 v = reinterpret_cast<const float4*>(x)[i4];
    reinterpret_cast<__half2*>(g_xnh)[i4 * 2] =
        __floats2half2_rn(v.x * sw + sb, v.y * sw + sb);
    reinterpret_cast<__half2*>(g_xnh)[i4 * 2 + 1] =
        __floats2half2_rn(v.z * sw + sb, v.w * sw + sb);
}

// ---------------------------------------------------------------------------
// 3. QKV GEMM, fp16 tensor cores. Out = W @ xn + bias.
//    Q -> g_qh[t][o] pre-scaled; K -> g_kh[t][o-128]; V -> g_vh[o-256][t].
// ---------------------------------------------------------------------------
#define QKV_SMEM (16384 + 32768)

__global__ void __launch_bounds__(256) qkv_h_kernel(const float* __restrict__ W,
                                                    const float* __restrict__ bias) {
    extern __shared__ char qs[];
    uint32_t ws_u, xs_u;
    asm("{ .reg .u64 t; cvta.to.shared.u64 t, %1; cvt.u32.u64 %0, t; }"
        : "=r"(ws_u) : "l"(qs));
    xs_u = ws_u + 16384;

    const int b = blockIdx.z;
    const int ob0 = blockIdx.y * 64;
    const int t0 = blockIdx.x * 128;
    const int tid = threadIdx.x, warp = tid >> 5, lane = tid & 31;
    const int lr = lane >> 2, lc = lane & 3, r8 = lane & 7, j8 = lane >> 3;

    // ---- W tile: [64 o][128 c] fp32 -> fp16, swizzled ----
    {
        int row = tid >> 2;
#pragma unroll
        for (int i = 0; i < 4; i++) {
            int g = (tid & 3) * 4 + i;
            const float* wp = W + (size_t)(ob0 + row) * CDIM + g * 8;
            float4 wa = *(const float4*)wp;
            float4 wb = *(const float4*)(wp + 4);
            sts128u(ws_u + row * 256 + ((g ^ (row & 7)) << 4),
                    packh2(wa.x, wa.y), packh2(wa.z, wa.w),
                    packh2(wb.x, wb.y), packh2(wb.z, wb.w));
        }
    }
    // ---- X tile: [128 c][128 t] fp16 via cp.async ----
    {
        int tg = tid & 15, c0 = (tid >> 4) * 8;
        const __half* xp = g_xnh + (size_t)b * CDIM * HWDIM;
#pragma unroll
        for (int j = 0; j < 8; j++) {
            int c = c0 + j;
            cpa16(xs_u + c * 256 + ((tg ^ (c & 7)) << 4),
                  xp + (size_t)c * HWDIM + t0 + tg * 8);
        }
        asm volatile("cp.async.commit_group;" ::: "memory");
    }
    asm volatile("cp.async.wait_group 0;" ::: "memory");
    __syncthreads();

    const int wm = warp & 1, wn = warp >> 1;
    float acc[4][2][4];
#pragma unroll
    for (int mi = 0; mi < 4; mi++)
#pragma unroll
        for (int n8 = 0; n8 < 2; n8++)
#pragma unroll
            for (int c = 0; c < 4; c++) acc[mi][n8][c] = 0.f;

#pragma unroll
    for (int ks = 0; ks < 4; ks++) {
        uint32_t bf[2][4];
#pragma unroll
        for (int n8 = 0; n8 < 2; n8++) {
            int row = wn * 16 + n8 * 8 + r8;
            ldm4(bf[n8], ws_u + row * 256 + (((ks * 4 + j8) ^ (row & 7)) << 4));
        }
        uint32_t af[4][2][4];
#pragma unroll
        for (int mi = 0; mi < 4; mi++)
#pragma unroll
            for (int kh = 0; kh < 2; kh++) {
                int c_row = ks * 32 + kh * 16 + (lane & 7) + ((lane >> 4) & 1) * 8;
                int tg = wm * 8 + mi * 2 + ((lane >> 3) & 1);
                ldm4t(af[mi][kh], xs_u + c_row * 256 + ((tg ^ (c_row & 7)) << 4));
            }
#pragma unroll
        for (int mi = 0; mi < 4; mi++)
#pragma unroll
            for (int n8 = 0; n8 < 2; n8++) {
                mma16(acc[mi][n8], af[mi][0], bf[n8][0], bf[n8][1]);
                mma16(acc[mi][n8], af[mi][1], bf[n8][2], bf[n8][3]);
            }
    }

    // ---- epilogue ----
    const float QSC = 0.088388347648318447f * 1.4426950408889634f;  // C^-0.5 * log2(e)
#pragma unroll
    for (int mi = 0; mi < 4; mi++) {
        int t = t0 + wm * 64 + mi * 16 + lr;
#pragma unroll
        for (int n8 = 0; n8 < 2; n8++) {
            int o = ob0 + wn * 16 + n8 * 8 + 2 * lc;
            float b0 = bias[o], b1 = bias[o + 1];
            float v0 = acc[mi][n8][0] + b0, v1 = acc[mi][n8][1] + b1;
            float v2 = acc[mi][n8][2] + b0, v3 = acc[mi][n8][3] + b1;
            if (ob0 < 128) {          // Q: [t][o], pre-scaled
                *(__half2*)(g_qh + ((size_t)b * HWDIM + t) * CDIM + o) =
                    __floats2half2_rn(v0 * QSC, v1 * QSC);
                *(__half2*)(g_qh + ((size_t)b * HWDIM + t + 8) * CDIM + o) =
                    __floats2half2_rn(v2 * QSC, v3 * QSC);
            } else if (ob0 < 256) {   // K: [t][o-128]
                *(__half2*)(g_kh + ((size_t)b * HWDIM + t) * CDIM + (o - 128)) =
                    __floats2half2_rn(v0, v1);
                *(__half2*)(g_kh + ((size_t)b * HWDIM + t + 8) * CDIM + (o - 128)) =
                    __floats2half2_rn(v2, v3);
            } else {                  // V: [ch][t]
                __half* vv = g_vh + (size_t)b * CDIM * HWDIM;
                vv[(size_t)(o - 256) * HWDIM + t]     = __float2half(v0);
                vv[(size_t)(o - 255) * HWDIM + t]     = __float2half(v1);
                vv[(size_t)(o - 256) * HWDIM + t + 8] = __float2half(v2);
                vv[(size_t)(o - 255) * HWDIM + t + 8] = __float2half(v3);
            }
        }
    }
}

// ---------------------------------------------------------------------------
// 4. Flash attention (R12 configuration, best measured: 102.2 us):
//    fp16 mma, register-resident P, direct cp.async staging, 64-key tiles
//    in two 32-key halves, double buffer, 16KB smem.
//    256 threads, 8 warps x 32 q = 256 q/CTA.
// ---------------------------------------------------------------------------
#define NT (HWDIM / 64)

__global__ void __launch_bounds__(256, 2) attn_mma_kernel() {
    __shared__ __align__(16) char smem[16384];
    uint32_t smem_u;
    asm("{ .reg .u64 t; cvta.to.shared.u64 t, %1; cvt.u32.u64 %0, t; }"
        : "=r"(smem_u) : "l"(smem));

    const int b = blockIdx.z, h = blockIdx.y;
    const int q0 = blockIdx.x * 256;
    const int tid = threadIdx.x;
    const int warp = tid >> 5, lane = tid & 31;
    const int lr = lane >> 2, lc = lane & 3;
    const int r8 = lane & 7, j8 = lane >> 3;
    const int qbase = warp * 32;

    const __half* Qh = g_qh + (size_t)b * HWDIM * CDIM;
    const __half* Kh = g_kh + (size_t)b * HWDIM * CDIM;
    const __half* Vh = g_vh + ((size_t)b * CDIM + h * HD) * HWDIM;

    // tile-load indices: 1 K chunk + 1 V chunk per thread
    const int lk_key = tid >> 2, lk_g = tid & 3;   // K: row=key(64), 4x16B chunks
    const int lv_ch  = tid >> 3, lv_g = tid & 7;   // V: row=ch(32), 8x16B chunks

    // ---- stage tile 0 into buf 0 ----
    cpa16(smem_u + lk_key * 64 + ((lk_g ^ ((lk_key >> 1) & 3)) << 4),
          Kh + (size_t)lk_key * CDIM + h * HD + lk_g * 8);
    cpa16(smem_u + 8192 + lv_ch * 128 + ((lv_g ^ (lv_ch & 7)) << 4),
          Vh + (size_t)lv_ch * HWDIM + lv_g * 8);
    asm volatile("cp.async.commit_group;" ::: "memory");

    // ---- Q fragments (fp16 pre-scaled) ----
    uint32_t qa[2][2][4];
#pragma unroll
    for (int mf = 0; mf < 2; mf++) {
        int qrow = q0 + qbase + mf * 16 + lr;
#pragma unroll
        for (int ks = 0; ks < 2; ks++) {
            int cc = h * HD + 2 * lc + 16 * ks;
            qa[mf][ks][0] = *(const uint32_t*)(Qh + (size_t)qrow * CDIM + cc);
            qa[mf][ks][1] = *(const uint32_t*)(Qh + (size_t)(qrow + 8) * CDIM + cc);
            qa[mf][ks][2] = *(const uint32_t*)(Qh + (size_t)qrow * CDIM + cc + 8);
            qa[mf][ks][3] = *(const uint32_t*)(Qh + (size_t)(qrow + 8) * CDIM + cc + 8);
        }
    }

    float l_i[2][2] = {{0.f, 0.f}, {0.f, 0.f}};
    float oacc[2][4][4];
#pragma unroll
    for (int mf = 0; mf < 2; mf++)
#pragma unroll
        for (int nf = 0; nf < 4; nf++)
#pragma unroll
            for (int c = 0; c < 4; c++) oacc[mf][nf][c] = 0.f;

    for (int t = 0; t < NT; t++) {
        // ---- stage tile t+1 into the other buffer ----
        if (t < NT - 1) {
            const int j0n = (t + 1) * 64;
            const int nb = (t + 1) & 1;
            cpa16(smem_u + nb * 4096 + lk_key * 64 + ((lk_g ^ ((lk_key >> 1) & 3)) << 4),
                  Kh + (size_t)(j0n + lk_key) * CDIM + h * HD + lk_g * 8);
            cpa16(smem_u + 8192 + nb * 4096 + lv_ch * 128 + ((lv_g ^ (lv_ch & 7)) << 4),
                  Vh + (size_t)lv_ch * HWDIM + j0n + lv_g * 8);
            asm volatile("cp.async.commit_group;" ::: "memory");
            asm volatile("cp.async.wait_group 1;" ::: "memory");
        } else {
            asm volatile("cp.async.wait_group 0;" ::: "memory");
        }
        __syncthreads();  // tile t visible to all threads

        const uint32_t kfb = smem_u + (t & 1) * 4096;
        const uint32_t vfb = smem_u + 8192 + (t & 1) * 4096;

        // ==== process tile in two 32-key halves (bounded liveness) ====
#pragma unroll
        for (int hh2 = 0; hh2 < 2; hh2++) {
            // ---- S = Q @ K^T for keys [32*hh2, 32*hh2+32) ----
            float sacc[2][4][4];
#pragma unroll
            for (int mf = 0; mf < 2; mf++)
#pragma unroll
                for (int nfl = 0; nfl < 4; nfl++)
#pragma unroll
                    for (int c = 0; c < 4; c++) sacc[mf][nfl][c] = 0.f;

#pragma unroll
            for (int nfl = 0; nfl < 4; nfl++) {
                uint32_t kb[4];
                int row = hh2 * 32 + nfl * 8 + r8;
                ldm4(kb, kfb + row * 64 + ((j8 ^ ((row >> 1) & 3)) << 4));
#pragma unroll
                for (int mf = 0; mf < 2; mf++) {
                    mma16(sacc[mf][nfl], qa[mf][0], kb[0], kb[1]);
                    mma16(sacc[mf][nfl], qa[mf][1], kb[2], kb[3]);
                }
            }

            // ---- exp2 -> fp16 P (registers), row sums ----
            uint32_t ph[2][2][4];
#pragma unroll
            for (int mf = 0; mf < 2; mf++) {
#pragma unroll
                for (int nfl = 0; nfl < 4; nfl++) {
                    ph[mf][0][nfl] = h2ex2(packh2(sacc[mf][nfl][0], sacc[mf][nfl][1]));
                    ph[mf][1][nfl] = h2ex2(packh2(sacc[mf][nfl][2], sacc[mf][nfl][3]));
                }
#pragma unroll
                for (int ri = 0; ri < 2; ri++) {
                    const uint32_t* p = ph[mf][ri];
                    __half2 s0 = __hadd2(*(__half2*)&p[0], *(__half2*)&p[1]);
                    __half2 s1 = __hadd2(*(__half2*)&p[2], *(__half2*)&p[3]);
                    __half2 s = __hadd2(s0, s1);
                    float2 f = __half22float2(s);
                    float sum = f.x + f.y;
                    sum += __shfl_xor_sync(0xffffffffu, sum, 1);
                    sum += __shfl_xor_sync(0xffffffffu, sum, 2);
                    l_i[mf][ri] += sum;
                }
            }

            // ---- V b-frags for this key half ----
            uint32_t vbl[4][4];
#pragma unroll
            for (int nf = 0; nf < 4; nf++) {
                int row = nf * 8 + r8;
                int g = hh2 * 4 + j8;
                ldm4(vbl[nf], vfb + row * 128 + ((g ^ r8) << 4));
            }

            // ---- O += P @ V (A-frags direct from ph registers) ----
#pragma unroll
            for (int mf = 0; mf < 2; mf++) {
#pragma unroll
                for (int kql = 0; kql < 2; kql++) {
                    uint32_t pa[4] = {ph[mf][0][2 * kql], ph[mf][1][2 * kql],
                                      ph[mf][0][2 * kql + 1], ph[mf][1][2 * kql + 1]};
#pragma unroll
                    for (int nf = 0; nf < 4; nf++)
                        mma16(oacc[mf][nf], pa, vbl[nf][2 * kql], vbl[nf][2 * kql + 1]);
                }
            }
        }
        __syncthreads();  // all reads of buf t&1 done before it is re-staged
    }

    // ---- epilogue: fp16 [t][c] output ----
#pragma unroll
    for (int mf = 0; mf < 2; mf++)
#pragma unroll
        for (int ri = 0; ri < 2; ri++) {
            float inv = 1.f / l_i[mf][ri];
            int q = q0 + qbase + mf * 16 + lr + 8 * ri;
#pragma unroll
            for (int nf = 0; nf < 4; nf++) {
                int ch = h * HD + nf * 8 + 2 * lc;
                *(uint32_t*)(g_atth + ((size_t)b * HWDIM + q) * CDIM + ch) =
                    packh2(oacc[mf][nf][2 * ri] * inv, oacc[mf][nf][2 * ri + 1] * inv);
            }
        }
}

// ---------------------------------------------------------------------------
// 5. Projection GEMM, fp16 tensor cores; epilogue adds bias + recomputed
//    GroupNorm residual (from x, mean, rstd, w, b) in fp32.
// ---------------------------------------------------------------------------
#define PROJ_SMEM (16384 + 32768)

__global__ void __launch_bounds__(256) proj_h_kernel(const float* __restrict__ W,
                                                     const float* __restrict__ bias,
                                                     float* __restrict__ Out,
                                                     const float* __restrict__ x,
                                                     const float* __restrict__ gnw,
                                                     const float* __restrict__ gnb) {
    extern __shared__ char qs[];
    uint32_t ws_u, as_u;
    asm("{ .reg .u64 t; cvta.to.shared.u64 t, %1; cvt.u32.u64 %0, t; }"
        : "=r"(ws_u) : "l"(qs));
    as_u = ws_u + 16384;

    const int b = blockIdx.z;
    const int ob0 = blockIdx.y * 64;
    const int t0 = blockIdx.x * 128;
    const int tid = threadIdx.x, warp = tid >> 5, lane = tid & 31;
    const int lr = lane >> 2, lc = lane & 3, r8 = lane & 7, j8 = lane >> 3;

    // ---- W tile ----
    {
        int row = tid >> 2;
#pragma unroll
        for (int i = 0; i < 4; i++) {
            int g = (tid & 3) * 4 + i;
            const float* wp = W + (size_t)(ob0 + row) * CDIM + g * 8;
            float4 wa = *(const float4*)wp;
            float4 wb = *(const float4*)(wp + 4);
            sts128u(ws_u + row * 256 + ((g ^ (row & 7)) << 4),
                    packh2(wa.x, wa.y), packh2(wa.z, wa.w),
                    packh2(wb.x, wb.y), packh2(wb.z, wb.w));
        }
    }
    // ---- A tile: [128 t][128 c] fp16 via cp.async ----
    {
        int tg = tid & 15, row0 = tid >> 4;
        const __half* ap = g_atth + (size_t)b * HWDIM * CDIM;
#pragma unroll
        for (int j = 0; j < 8; j++) {
            int row = row0 + 16 * j;
            cpa16(as_u + row * 256 + ((tg ^ (row & 7)) << 4),
                  ap + (size_t)(t0 + row) * CDIM + tg * 8);
        }
        asm volatile("cp.async.commit_group;" ::: "memory");
    }
    asm volatile("cp.async.wait_group 0;" ::: "memory");
    __syncthreads();

    const int wm = warp & 1, wn = warp >> 1;
    float acc[4][2][4];
#pragma unroll
    for (int mi = 0; mi < 4; mi++)
#pragma unroll
        for (int n8 = 0; n8 < 2; n8++)
#pragma unroll
            for (int c = 0; c < 4; c++) acc[mi][n8][c] = 0.f;

#pragma unroll
    for (int ks = 0; ks < 4; ks++) {
        uint32_t bf[2][4];
#pragma unroll
        for (int n8 = 0; n8 < 2; n8++) {
            int row = wn * 16 + n8 * 8 + r8;
            ldm4(bf[n8], ws_u + row * 256 + (((ks * 4 + j8) ^ (row & 7)) << 4));
        }
        uint32_t af[4][2][4];
#pragma unroll
        for (int mi = 0; mi < 4; mi++)
#pragma unroll
            for (int kh = 0; kh < 2; kh++) {
                int row = wm * 64 + mi * 16 + ((j8 & 1) << 3) + r8;
                int g = ks * 4 + kh * 2 + (j8 >> 1);
                ldm4(af[mi][kh], as_u + row * 256 + ((g ^ (row & 7)) << 4));
            }
#pragma unroll
        for (int mi = 0; mi < 4; mi++)
#pragma unroll
            for (int n8 = 0; n8 < 2; n8++) {
                mma16(acc[mi][n8], af[mi][0], bf[n8][0], bf[n8][1]);
                mma16(acc[mi][n8], af[mi][1], bf[n8][2], bf[n8][3]);
            }
    }

    // ---- epilogue: fp32 + bias + recomputed GN residual ----
#pragma unroll
    for (int mi = 0; mi < 4; mi++) {
        int t = t0 + wm * 64 + mi * 16 + lr;
#pragma unroll
        for (int n8 = 0; n8 < 2; n8++) {
            int o = ob0 + wn * 16 + n8 * 8 + 2 * lc;
            int bg = b * NGROUP + o / CPG;
            float mean = g_mean[bg], rstd = g_rstd[bg];
            float sw0 = gnw[o] * rstd,     sb0 = gnb[o] - mean * sw0;
            float sw1 = gnw[o + 1] * rstd, sb1 = gnb[o + 1] - mean * sw1;
            float b0 = bias[o], b1 = bias[o + 1];
            size_t i00 = ((size_t)b * CDIM + o) * HWDIM + t;
            size_t i10 = i00 + HWDIM;
            Out[i00]     = acc[mi][n8][0] + b0 + x[i00] * sw0 + sb0;
            Out[i10]     = acc[mi][n8][1] + b1 + x[i10] * sw1 + sb1;
            Out[i00 + 8] = acc[mi][n8][2] + b0 + x[i00 + 8] * sw0 + sb0;
            Out[i10 + 8] = acc[mi][n8][3] + b1 + x[i10 + 8] * sw1 + sb1;
        }
    }
}

// ---------------------------------------------------------------------------
// Launch
// ---------------------------------------------------------------------------
extern "C" void kernel_launch(void* const* d_in, const int* in_sizes, int n_in,
                              void* d_out, int out_size) {
    const float* x      = (const float*)d_in[0];
    const float* gn_w   = (const float*)d_in[1];
    const float* gn_b   = (const float*)d_in[2];
    const float* qkv_w  = (const float*)d_in[3];
    const float* qkv_b  = (const float*)d_in[4];
    const float* proj_w = (const float*)d_in[5];
    const float* proj_b = (const float*)d_in[6];
    float* out = (float*)d_out;

    static bool attr_set = false;
    if (!attr_set) {
        cudaFuncSetAttribute(qkv_h_kernel,
                             cudaFuncAttributeMaxDynamicSharedMemorySize, QKV_SMEM);
        cudaFuncSetAttribute(proj_h_kernel,
                             cudaFuncAttributeMaxDynamicSharedMemorySize, PROJ_SMEM);
        attr_set = true;
    }

    gn_stats_kernel<<<BATCH * NGROUP, 256>>>(x);
    gn_apply_kernel<<<(BATCH * CDIM * HWDIM / 4 + 255) / 256, 256>>>(x, gn_w, gn_b);
    qkv_h_kernel<<<dim3(HWDIM / 128, OC / 64, BATCH), 256, QKV_SMEM>>>(qkv_w, qkv_b);
    attn_mma_kernel<<<dim3(HWDIM / 256, NH, BATCH), 256>>>();
    proj_h_kernel<<<dim3(HWDIM / 128, CDIM / 64, BATCH), 256, PROJ_SMEM>>>(
        proj_w, proj_b, out, x, gn_w, gn_b);
}